// round 5
// baseline (speedup 1.0000x reference)
#include <cuda_runtime.h>
#include <cuda_bf16.h>
#include <math.h>
#include <stdint.h>

#define HH 128
#define WW 256
#define CC 192
#define HWP (128*256)
#define NB 2
#define LOG2E 1.4426950408889634f

// ---------------- scratch (device globals) ----------------------------------
__device__ float g_gate[NB * CC * HWP];
__device__ float g_t[NB * 3 * CC * HWP];
__device__ float g_qkv[NB * 3 * CC * HWP];
__device__ __nv_bfloat16 g_xhi[NB * CC * HWP];
__device__ __nv_bfloat16 g_xlo[NB * CC * HWP];
__device__ __nv_bfloat16 g_ahi[NB * CC * HWP];
__device__ __nv_bfloat16 g_alo[NB * CC * HWP];
__device__ __nv_bfloat16 g_yhi[NB * CC * HWP];
__device__ __nv_bfloat16 g_ylo[NB * CC * HWP];
__device__ __nv_bfloat16 g_whi[6 * CC * CC];
__device__ __nv_bfloat16 g_wlo[6 * CC * CC];

// ---------------- helpers -----------------------------------------------------
__device__ __forceinline__ uint32_t smem_u32(const void* p) {
    uint32_t a;
    asm("{ .reg .u64 t; cvta.to.shared.u64 t, %1; cvt.u32.u64 %0, t; }" : "=r"(a) : "l"(p));
    return a;
}
__device__ __forceinline__ void mma16816(float* c, const uint32_t* a,
                                         uint32_t b0, uint32_t b1)
{
    asm volatile(
        "mma.sync.aligned.m16n8k16.row.col.f32.bf16.bf16.f32 "
        "{%0,%1,%2,%3}, {%4,%5,%6,%7}, {%8,%9}, {%0,%1,%2,%3};\n"
        : "+f"(c[0]), "+f"(c[1]), "+f"(c[2]), "+f"(c[3])
        : "r"(a[0]), "r"(a[1]), "r"(a[2]), "r"(a[3]), "r"(b0), "r"(b1));
}
__device__ __forceinline__ void ldsm_x4(uint32_t* d, uint32_t a) {
    asm volatile("ldmatrix.sync.aligned.m8n8.x4.shared.b16 {%0,%1,%2,%3}, [%4];\n"
                 : "=r"(d[0]), "=r"(d[1]), "=r"(d[2]), "=r"(d[3]) : "r"(a));
}
__device__ __forceinline__ void ldsm_x2(uint32_t& d0, uint32_t& d1, uint32_t a) {
    asm volatile("ldmatrix.sync.aligned.m8n8.x2.shared.b16 {%0,%1}, [%2];\n"
                 : "=r"(d0), "=r"(d1) : "r"(a));
}
__device__ __forceinline__ void ldsm_x2_t(uint32_t& d0, uint32_t& d1, uint32_t a) {
    asm volatile("ldmatrix.sync.aligned.m8n8.x2.trans.shared.b16 {%0,%1}, [%2];\n"
                 : "=r"(d0), "=r"(d1) : "r"(a));
}
__device__ __forceinline__ uint32_t pack_bf2(__nv_bfloat16 a, __nv_bfloat16 b) {
    __nv_bfloat162 t; t.x = a; t.y = b; return *(uint32_t*)&t;
}

// ---------------- fp32 -> (hi,lo) bf16 split, 4/thread ----------------------
__global__ void __launch_bounds__(256) split4_kernel(
    const float* __restrict__ x, __nv_bfloat16* __restrict__ hi,
    __nv_bfloat16* __restrict__ lo, int n4)
{
    int i = blockIdx.x * 256 + threadIdx.x;
    if (i < n4) {
        float4 v = ((const float4*)x)[i];
        float vs[4] = {v.x, v.y, v.z, v.w};
        __nv_bfloat16 h[4], l[4];
#pragma unroll
        for (int j = 0; j < 4; j++) {
            h[j] = __float2bfloat16(vs[j]);
            l[j] = __float2bfloat16(vs[j] - __bfloat162float(h[j]));
        }
        ((uint2*)hi)[i] = *(uint2*)h;
        ((uint2*)lo)[i] = *(uint2*)l;
    }
}

// ---------------- split-bf16 tensor-core GEMM (R3, passing) ------------------
#define BROW 264

__global__ void __launch_bounds__(256, 2) gemm_bf16_kernel(
    const __nv_bfloat16* __restrict__ Whi, const __nv_bfloat16* __restrict__ Wlo,
    const __nv_bfloat16* __restrict__ Xhi, const __nv_bfloat16* __restrict__ Xlo,
    float* __restrict__ Yf, const float* __restrict__ G,
    __nv_bfloat16* __restrict__ Yhi, __nv_bfloat16* __restrict__ Ylo,
    int M, int epi)
{
    __shared__ __align__(16) __nv_bfloat16 Bs[2][2][16][BROW];

    const int b  = blockIdx.z;
    const int m0 = blockIdx.y * 64;
    const int n0 = blockIdx.x * 256;
    const size_t xoff = (size_t)b * CC * HWP;

    const int tid  = threadIdx.x;
    const int lane = tid & 31;
    const int warp = tid >> 5;
    const int wm   = (warp >> 2) * 32;
    const int wn   = (warp & 3) * 64;
    const int gq   = lane >> 2;
    const int tg   = lane & 3;
    const int bn2  = 2 * lane;

    const uint32_t bs_base = (uint32_t)__cvta_generic_to_shared(&Bs[0][0][0][0]);
    const int krow = lane & 15;
    const uint32_t lrow = krow * (BROW * 2) + wn * 2;

    float acc[2][8][4];
#pragma unroll
    for (int mt = 0; mt < 2; mt++)
#pragma unroll
        for (int nt = 0; nt < 8; nt++)
#pragma unroll
            for (int i = 0; i < 4; i++) acc[mt][nt][i] = 0.f;

    uint32_t bh[2][4], bl[2][4];
#pragma unroll
    for (int r = 0; r < 2; r++) {
        const int k = warp + 8 * r;
#pragma unroll
        for (int j = 0; j < 4; j++) {
            const size_t off = xoff + (size_t)k * HWP + n0 + bn2 + 64 * j;
            bh[r][j] = *(const uint32_t*)(Xhi + off);
            bl[r][j] = *(const uint32_t*)(Xlo + off);
        }
    }
#pragma unroll
    for (int r = 0; r < 2; r++) {
        const int k = warp + 8 * r;
#pragma unroll
        for (int j = 0; j < 4; j++) {
            *(uint32_t*)&Bs[0][0][k][bn2 + 64 * j] = bh[r][j];
            *(uint32_t*)&Bs[0][1][k][bn2 + 64 * j] = bl[r][j];
        }
    }
    __syncthreads();

    const int NK = CC / 16;
    for (int i = 0; i < NK; i++) {
        const int buf = i & 1;
        const int k0  = i * 16;
        if (i + 1 < NK) {
#pragma unroll
            for (int r = 0; r < 2; r++) {
                const int k = k0 + 16 + warp + 8 * r;
#pragma unroll
                for (int j = 0; j < 4; j++) {
                    const size_t off = xoff + (size_t)k * HWP + n0 + bn2 + 64 * j;
                    bh[r][j] = *(const uint32_t*)(Xhi + off);
                    bl[r][j] = *(const uint32_t*)(Xlo + off);
                }
            }
        }
        uint32_t af[2][2][4];
#pragma unroll
        for (int mt = 0; mt < 2; mt++) {
            const size_t r0 = (size_t)(m0 + wm + mt * 16 + gq) * CC + k0 + 2 * tg;
            const size_t r1 = r0 + 8 * CC;
            af[0][mt][0] = *(const uint32_t*)(Whi + r0);
            af[0][mt][1] = *(const uint32_t*)(Whi + r1);
            af[0][mt][2] = *(const uint32_t*)(Whi + r0 + 8);
            af[0][mt][3] = *(const uint32_t*)(Whi + r1 + 8);
            af[1][mt][0] = *(const uint32_t*)(Wlo + r0);
            af[1][mt][1] = *(const uint32_t*)(Wlo + r1);
            af[1][mt][2] = *(const uint32_t*)(Wlo + r0 + 8);
            af[1][mt][3] = *(const uint32_t*)(Wlo + r1 + 8);
        }
        const uint32_t hb0 = bs_base + (uint32_t)(buf * 2 + 0) * (16 * BROW * 2) + lrow;
        const uint32_t hb1 = bs_base + (uint32_t)(buf * 2 + 1) * (16 * BROW * 2) + lrow;
#pragma unroll
        for (int nt = 0; nt < 8; nt++) {
            uint32_t b0, b1, c0, c1;
            ldsm_x2_t(b0, b1, hb0 + nt * 16);
            ldsm_x2_t(c0, c1, hb1 + nt * 16);
#pragma unroll
            for (int mt = 0; mt < 2; mt++) {
                mma16816(acc[mt][nt], af[0][mt], b0, b1);
                mma16816(acc[mt][nt], af[0][mt], c0, c1);
                mma16816(acc[mt][nt], af[1][mt], b0, b1);
            }
        }
        if (i + 1 < NK) {
            const int nb = buf ^ 1;
#pragma unroll
            for (int r = 0; r < 2; r++) {
                const int k = warp + 8 * r;
#pragma unroll
                for (int j = 0; j < 4; j++) {
                    *(uint32_t*)&Bs[nb][0][k][bn2 + 64 * j] = bh[r][j];
                    *(uint32_t*)&Bs[nb][1][k][bn2 + 64 * j] = bl[r][j];
                }
            }
        }
        __syncthreads();
    }

    const size_t yoff = (size_t)b * M * HWP;
    const size_t goff = (size_t)b * CC * HWP;
#pragma unroll
    for (int mt = 0; mt < 2; mt++) {
        const int r0 = m0 + wm + mt * 16 + gq;
        const int r1 = r0 + 8;
#pragma unroll
        for (int nt = 0; nt < 8; nt++) {
            const int c = n0 + wn + nt * 8 + 2 * tg;
            float v00 = acc[mt][nt][0], v01 = acc[mt][nt][1];
            float v10 = acc[mt][nt][2], v11 = acc[mt][nt][3];
            if (epi == 1) {
                v00 = v00 / (1.f + __expf(-v00));
                v01 = v01 / (1.f + __expf(-v01));
                v10 = v10 / (1.f + __expf(-v10));
                v11 = v11 / (1.f + __expf(-v11));
            }
            if (epi == 2) {
                float2 g0 = *(const float2*)(G + goff + (size_t)r0 * HWP + c);
                float2 g1 = *(const float2*)(G + goff + (size_t)r1 * HWP + c);
                v00 *= g0.x; v01 *= g0.y; v10 *= g1.x; v11 *= g1.y;
                __nv_bfloat16 h00 = __float2bfloat16(v00);
                __nv_bfloat16 h01 = __float2bfloat16(v01);
                __nv_bfloat16 h10 = __float2bfloat16(v10);
                __nv_bfloat16 h11 = __float2bfloat16(v11);
                *(uint32_t*)(Yhi + yoff + (size_t)r0 * HWP + c) = pack_bf2(h00, h01);
                *(uint32_t*)(Yhi + yoff + (size_t)r1 * HWP + c) = pack_bf2(h10, h11);
                *(uint32_t*)(Ylo + yoff + (size_t)r0 * HWP + c) = pack_bf2(
                    __float2bfloat16(v00 - __bfloat162float(h00)),
                    __float2bfloat16(v01 - __bfloat162float(h01)));
                *(uint32_t*)(Ylo + yoff + (size_t)r1 * HWP + c) = pack_bf2(
                    __float2bfloat16(v10 - __bfloat162float(h10)),
                    __float2bfloat16(v11 - __bfloat162float(h11)));
            } else {
                *(float2*)(Yf + yoff + (size_t)r0 * HWP + c) = make_float2(v00, v01);
                *(float2*)(Yf + yoff + (size_t)r1 * HWP + c) = make_float2(v10, v11);
            }
        }
    }
}

// ---------------- depthwise 3x3, 4 px/thread --------------------------------
__global__ void __launch_bounds__(256) dw_kernel(
    const float* __restrict__ t, const float* __restrict__ wd, float* __restrict__ out)
{
    const int cb = blockIdx.y;
    const int c  = cb % (3 * CC);
    const int p  = (blockIdx.x * 256 + threadIdx.x) * 4;
    const int y  = p >> 8;
    const int x  = p & 255;
    const float* base = t + (size_t)cb * HWP;

    float w[9];
#pragma unroll
    for (int i = 0; i < 9; i++) w[i] = wd[c * 9 + i];

    float a0 = 0.f, a1 = 0.f, a2 = 0.f, a3 = 0.f;
#pragma unroll
    for (int dy = -1; dy <= 1; dy++) {
        const int yy = y + dy;
        if (yy < 0 || yy >= HH) continue;
        const float* r = base + yy * WW + x;
        const float4 f = *(const float4*)r;
        const float left  = (x > 0)   ? r[-1] : 0.f;
        const float right = (x < 252) ? r[4]  : 0.f;
        const float w0 = w[(dy + 1) * 3 + 0];
        const float w1 = w[(dy + 1) * 3 + 1];
        const float w2 = w[(dy + 1) * 3 + 2];
        a0 = fmaf(w0, left, fmaf(w1, f.x, fmaf(w2, f.y, a0)));
        a1 = fmaf(w0, f.x,  fmaf(w1, f.y, fmaf(w2, f.z, a1)));
        a2 = fmaf(w0, f.y,  fmaf(w1, f.z, fmaf(w2, f.w, a2)));
        a3 = fmaf(w0, f.z,  fmaf(w1, f.w, fmaf(w2, right, a3)));
    }
    *(float4*)(out + (size_t)cb * HWP + p) = make_float4(a0, a1, a2, a3);
}

// ---------------- attention via mma.sync (FA2-style, split-bf16) -------------
// block = (row, head, b), 8 warps x 32 queries, K/V in 64-key chunks.
#define ASM_Q 2048
#define ASM_K 43008
#define ASM_V 53248
#define ASM_TOTAL 63488

__global__ void __launch_bounds__(256) attn_mma_kernel(
    const float* __restrict__ qkv, const float* __restrict__ rpb,
    __nv_bfloat16* __restrict__ ohi, __nv_bfloat16* __restrict__ olo)
{
    extern __shared__ __align__(16) char asm_[];
    float* bsh = (float*)asm_;
    __nv_bfloat16* Qh = (__nv_bfloat16*)(asm_ + ASM_Q);
    __nv_bfloat16* Ql = Qh + 256 * 40;
    __nv_bfloat16* Kh = (__nv_bfloat16*)(asm_ + ASM_K);
    __nv_bfloat16* Kl = Kh + 64 * 40;
    __nv_bfloat16* Vh = (__nv_bfloat16*)(asm_ + ASM_V);
    __nv_bfloat16* Vl = Vh + 64 * 40;
    float* stage = (float*)(asm_ + ASM_Q);   // reused after chunks

    const int row = blockIdx.x, head = blockIdx.y, b = blockIdx.z;
    const int tid = threadIdx.x, lane = tid & 31, warp = tid >> 5;
    const int gq = lane >> 2, tg = lane & 3;
    const size_t base = (((size_t)b * (3 * CC) + head * 32) * HH + row) * WW;
    const size_t koff = (size_t)CC * HWP, voff = 2 * koff;
    const float scale = 0.17677669529663687f;

    for (int i = tid; i < 511; i += 256) bsh[i] = rpb[i * 6 + head];

    // Q load + split (q = tid, d = it)
#pragma unroll 4
    for (int it = 0; it < 32; it++) {
        float v = qkv[base + (size_t)it * HWP + tid];
        __nv_bfloat16 h = __float2bfloat16(v);
        Qh[tid * 40 + it] = h;
        Ql[tid * 40 + it] = __float2bfloat16(v - __bfloat162float(h));
    }
    __syncthreads();

    // Q fragments [half][mt][ks][4]
    uint32_t qf[2][2][2][4];
    {
        const int r = warp * 32 + (lane & 15);
        const int cb = (lane >> 4) * 8;
#pragma unroll
        for (int mt = 0; mt < 2; mt++)
#pragma unroll
            for (int ks = 0; ks < 2; ks++) {
                ldsm_x4(qf[0][mt][ks], smem_u32(&Qh[(r + mt * 16) * 40 + ks * 16 + cb]));
                ldsm_x4(qf[1][mt][ks], smem_u32(&Ql[(r + mt * 16) * 40 + ks * 16 + cb]));
            }
    }

    float m4[4] = {-1e30f, -1e30f, -1e30f, -1e30f};
    float l4[4] = {0.f, 0.f, 0.f, 0.f};
    float o[2][4][4];
#pragma unroll
    for (int mt = 0; mt < 2; mt++)
#pragma unroll
        for (int nt = 0; nt < 4; nt++)
#pragma unroll
            for (int e = 0; e < 4; e++) o[mt][nt][e] = 0.f;

    for (int jt = 0; jt < WW; jt += 64) {
        __syncthreads();
        // K/V chunk load + split (64 keys x 32 dims)
#pragma unroll
        for (int it = 0; it < 8; it++) {
            const int idx = it * 256 + tid;
            const int j = idx & 63, d = idx >> 6;
            const float kv = qkv[base + koff + (size_t)d * HWP + jt + j];
            const float vv = qkv[base + voff + (size_t)d * HWP + jt + j];
            __nv_bfloat16 kh = __float2bfloat16(kv);
            __nv_bfloat16 vh = __float2bfloat16(vv);
            Kh[j * 40 + d] = kh;
            Kl[j * 40 + d] = __float2bfloat16(kv - __bfloat162float(kh));
            Vh[j * 40 + d] = vh;
            Vl[j * 40 + d] = __float2bfloat16(vv - __bfloat162float(vh));
        }
        __syncthreads();

        // S = Q K^T (3-product split)
        float s[2][8][4];
#pragma unroll
        for (int mt = 0; mt < 2; mt++)
#pragma unroll
            for (int nt = 0; nt < 8; nt++)
#pragma unroll
                for (int e = 0; e < 4; e++) s[mt][nt][e] = 0.f;

        const int krow = (lane & 7);
        const int kcb = ((lane >> 3) & 1) * 8;
#pragma unroll
        for (int nt = 0; nt < 8; nt++) {
            uint32_t kf[2][2][2];
#pragma unroll
            for (int ks = 0; ks < 2; ks++) {
                ldsm_x2(kf[ks][0][0], kf[ks][0][1],
                        smem_u32(&Kh[(nt * 8 + krow) * 40 + ks * 16 + kcb]));
                ldsm_x2(kf[ks][1][0], kf[ks][1][1],
                        smem_u32(&Kl[(nt * 8 + krow) * 40 + ks * 16 + kcb]));
            }
#pragma unroll
            for (int mt = 0; mt < 2; mt++)
#pragma unroll
                for (int ks = 0; ks < 2; ks++) {
                    mma16816(s[mt][nt], qf[0][mt][ks], kf[ks][0][0], kf[ks][0][1]);
                    mma16816(s[mt][nt], qf[0][mt][ks], kf[ks][1][0], kf[ks][1][1]);
                    mma16816(s[mt][nt], qf[1][mt][ks], kf[ks][0][0], kf[ks][0][1]);
                }
        }

        // bias + scale + row max
        float pm[4] = {m4[0], m4[1], m4[2], m4[3]};
#pragma unroll
        for (int mt = 0; mt < 2; mt++) {
            const int i0 = warp * 32 + mt * 16 + gq;
#pragma unroll
            for (int nt = 0; nt < 8; nt++) {
                const int jb = jt + nt * 8 + 2 * tg;
#pragma unroll
                for (int e = 0; e < 4; e++) {
                    const int i = i0 + (e >> 1) * 8;
                    const int j = jb + (e & 1);
                    const float t = fmaf(s[mt][nt][e], scale, bsh[i - j + 255]);
                    s[mt][nt][e] = t;
                    const int sl = mt * 2 + (e >> 1);
                    pm[sl] = fmaxf(pm[sl], t);
                }
            }
        }
#pragma unroll
        for (int sl = 0; sl < 4; sl++) {
            float v = pm[sl];
            v = fmaxf(v, __shfl_xor_sync(0xFFFFFFFFu, v, 1));
            v = fmaxf(v, __shfl_xor_sync(0xFFFFFFFFu, v, 2));
            pm[sl] = v;
        }
        float cf[4];
#pragma unroll
        for (int sl = 0; sl < 4; sl++) {
            cf[sl] = exp2f((m4[sl] - pm[sl]) * LOG2E);
            m4[sl] = pm[sl];
            l4[sl] *= cf[sl];
        }
#pragma unroll
        for (int mt = 0; mt < 2; mt++)
#pragma unroll
            for (int nt = 0; nt < 4; nt++)
#pragma unroll
                for (int e = 0; e < 4; e++)
                    o[mt][nt][e] *= cf[mt * 2 + (e >> 1)];

        // P = exp(S - m); PV accumulation per 16-key step
        float rs[4] = {0.f, 0.f, 0.f, 0.f};
#pragma unroll
        for (int kp = 0; kp < 4; kp++) {
            uint32_t pfh[2][4], pfl[2][4];
#pragma unroll
            for (int h2 = 0; h2 < 2; h2++) {
                const int nt = 2 * kp + h2;
#pragma unroll
                for (int mt = 0; mt < 2; mt++) {
                    const float mA = m4[mt * 2 + 0], mB = m4[mt * 2 + 1];
                    float p0 = exp2f((s[mt][nt][0] - mA) * LOG2E);
                    float p1 = exp2f((s[mt][nt][1] - mA) * LOG2E);
                    float p2 = exp2f((s[mt][nt][2] - mB) * LOG2E);
                    float p3 = exp2f((s[mt][nt][3] - mB) * LOG2E);
                    rs[mt * 2 + 0] += p0 + p1;
                    rs[mt * 2 + 1] += p2 + p3;
                    __nv_bfloat16 h0 = __float2bfloat16(p0);
                    __nv_bfloat16 h1 = __float2bfloat16(p1);
                    __nv_bfloat16 h2b = __float2bfloat16(p2);
                    __nv_bfloat16 h3 = __float2bfloat16(p3);
                    pfh[mt][h2 * 2 + 0] = pack_bf2(h0, h1);
                    pfh[mt][h2 * 2 + 1] = pack_bf2(h2b, h3);
                    pfl[mt][h2 * 2 + 0] = pack_bf2(
                        __float2bfloat16(p0 - __bfloat162float(h0)),
                        __float2bfloat16(p1 - __bfloat162float(h1)));
                    pfl[mt][h2 * 2 + 1] = pack_bf2(
                        __float2bfloat16(p2 - __bfloat162float(h2b)),
                        __float2bfloat16(p3 - __bfloat162float(h3)));
                }
            }
            const int vrow = kp * 16 + (lane & 15);
#pragma unroll
            for (int ntv = 0; ntv < 4; ntv++) {
                uint32_t vh0, vh1, vl0, vl1;
                ldsm_x2_t(vh0, vh1, smem_u32(&Vh[vrow * 40 + ntv * 8]));
                ldsm_x2_t(vl0, vl1, smem_u32(&Vl[vrow * 40 + ntv * 8]));
#pragma unroll
                for (int mt = 0; mt < 2; mt++) {
                    mma16816(o[mt][ntv], pfh[mt], vh0, vh1);
                    mma16816(o[mt][ntv], pfh[mt], vl0, vl1);
                    mma16816(o[mt][ntv], pfl[mt], vh0, vh1);
                }
            }
        }
#pragma unroll
        for (int sl = 0; sl < 4; sl++) {
            float r = rs[sl];
            r += __shfl_xor_sync(0xFFFFFFFFu, r, 1);
            r += __shfl_xor_sync(0xFFFFFFFFu, r, 2);
            l4[sl] += r;
        }
    }

    // epilogue: normalize -> smem transpose -> coalesced split store
    __syncthreads();
    float inv[4];
#pragma unroll
    for (int sl = 0; sl < 4; sl++) inv[sl] = 1.f / l4[sl];
#pragma unroll
    for (int mt = 0; mt < 2; mt++) {
        const int r0 = warp * 32 + mt * 16 + gq;
#pragma unroll
        for (int nt = 0; nt < 4; nt++) {
            const int c = nt * 8 + 2 * tg;
#pragma unroll
            for (int e = 0; e < 4; e++) {
                const int rr = r0 + (e >> 1) * 8;
                stage[rr * 33 + c + (e & 1)] = o[mt][nt][e] * inv[mt * 2 + (e >> 1)];
            }
        }
    }
    __syncthreads();
    const size_t obase = (((size_t)b * CC + head * 32) * HH + row) * WW;
#pragma unroll 4
    for (int d = 0; d < 32; d++) {
        const float v = stage[tid * 33 + d];
        __nv_bfloat16 h = __float2bfloat16(v);
        ohi[obase + (size_t)d * HWP + tid] = h;
        olo[obase + (size_t)d * HWP + tid] = __float2bfloat16(v - __bfloat162float(h));
    }
}

// ---------------- launch ------------------------------------------------------
extern "C" void kernel_launch(void* const* d_in, const int* in_sizes, int n_in,
                              void* d_out, int out_size)
{
    const float* x       = (const float*)d_in[0];
    const float* rpb     = (const float*)d_in[1];
    const float* w_qkv   = (const float*)d_in[2];
    const float* w_depth = (const float*)d_in[3];
    const float* w_pre   = (const float*)d_in[4];
    const float* w_out   = (const float*)d_in[5];
    const float* w_gate  = (const float*)d_in[6];
    float* out = (float*)d_out;
    (void)in_sizes; (void)n_in; (void)out_size;

    float *gate, *t, *qkv;
    __nv_bfloat16 *xhi, *xlo, *ahi, *alo, *yhi, *ylo, *whi, *wlo;
    cudaGetSymbolAddress((void**)&gate, g_gate);
    cudaGetSymbolAddress((void**)&t,    g_t);
    cudaGetSymbolAddress((void**)&qkv,  g_qkv);
    cudaGetSymbolAddress((void**)&xhi,  g_xhi);
    cudaGetSymbolAddress((void**)&xlo,  g_xlo);
    cudaGetSymbolAddress((void**)&ahi,  g_ahi);
    cudaGetSymbolAddress((void**)&alo,  g_alo);
    cudaGetSymbolAddress((void**)&yhi,  g_yhi);
    cudaGetSymbolAddress((void**)&ylo,  g_ylo);
    cudaGetSymbolAddress((void**)&whi,  g_whi);
    cudaGetSymbolAddress((void**)&wlo,  g_wlo);

    cudaFuncSetAttribute(attn_mma_kernel,
                         cudaFuncAttributeMaxDynamicSharedMemorySize, ASM_TOTAL);

    const int WQ = 3 * CC * CC;
    const int WS = CC * CC;
    split4_kernel<<<(WQ / 4 + 255) / 256, 256>>>(w_qkv,  whi,          wlo,          WQ / 4);
    split4_kernel<<<(WS / 4 + 255) / 256, 256>>>(w_pre,  whi + 3 * WS, wlo + 3 * WS, WS / 4);
    split4_kernel<<<(WS / 4 + 255) / 256, 256>>>(w_out,  whi + 4 * WS, wlo + 4 * WS, WS / 4);
    split4_kernel<<<(WS / 4 + 255) / 256, 256>>>(w_gate, whi + 5 * WS, wlo + 5 * WS, WS / 4);

    const int nx = NB * CC * HWP;
    split4_kernel<<<(nx / 4 + 255) / 256, 256>>>(x, xhi, xlo, nx / 4);

    const dim3 gSmall(HWP / 256, CC / 64, NB);
    const dim3 gQkv(HWP / 256, 3 * CC / 64, NB);

    gemm_bf16_kernel<<<gSmall, 256>>>(whi + 5 * WS, wlo + 5 * WS, xhi, xlo,
                                      gate, nullptr, nullptr, nullptr, CC, 1);
    gemm_bf16_kernel<<<gQkv, 256>>>(whi, wlo, xhi, xlo,
                                    t, nullptr, nullptr, nullptr, 3 * CC, 0);
    dw_kernel<<<dim3(HWP / 1024, NB * 3 * CC), 256>>>(t, w_depth, qkv);
    attn_mma_kernel<<<dim3(HH, 6, NB), 256, ASM_TOTAL>>>(qkv, rpb, ahi, alo);
    gemm_bf16_kernel<<<gSmall, 256>>>(whi + 3 * WS, wlo + 3 * WS, ahi, alo,
                                      nullptr, gate, yhi, ylo, CC, 2);
    gemm_bf16_kernel<<<gSmall, 256>>>(whi + 4 * WS, wlo + 4 * WS, yhi, ylo,
                                      out, nullptr, nullptr, nullptr, CC, 0);
}

// round 6
// speedup vs baseline: 1.3170x; 1.3170x over previous
#include <cuda_runtime.h>
#include <cuda_bf16.h>
#include <math.h>
#include <stdint.h>

#define HH 128
#define WW 256
#define CC 192
#define HWP (128*256)
#define NB 2

// ---------------- scratch (device globals) ----------------------------------
__device__ float g_gate[NB * CC * HWP];
__device__ float g_t[NB * 3 * CC * HWP];
__device__ float g_qkv[NB * 3 * CC * HWP];
__device__ __nv_bfloat16 g_xhi[NB * CC * HWP];
__device__ __nv_bfloat16 g_xlo[NB * CC * HWP];
__device__ __nv_bfloat16 g_ahi[NB * CC * HWP];
__device__ __nv_bfloat16 g_alo[NB * CC * HWP];
__device__ __nv_bfloat16 g_yhi[NB * CC * HWP];
__device__ __nv_bfloat16 g_ylo[NB * CC * HWP];
__device__ __nv_bfloat16 g_whi[6 * CC * CC];
__device__ __nv_bfloat16 g_wlo[6 * CC * CC];

// ---------------- helpers -----------------------------------------------------
__device__ __forceinline__ uint32_t smem_u32(const void* p) {
    uint32_t a;
    asm("{ .reg .u64 t; cvta.to.shared.u64 t, %1; cvt.u32.u64 %0, t; }" : "=r"(a) : "l"(p));
    return a;
}
__device__ __forceinline__ void mma16816(float* c, const uint32_t* a,
                                         uint32_t b0, uint32_t b1)
{
    asm volatile(
        "mma.sync.aligned.m16n8k16.row.col.f32.bf16.bf16.f32 "
        "{%0,%1,%2,%3}, {%4,%5,%6,%7}, {%8,%9}, {%0,%1,%2,%3};\n"
        : "+f"(c[0]), "+f"(c[1]), "+f"(c[2]), "+f"(c[3])
        : "r"(a[0]), "r"(a[1]), "r"(a[2]), "r"(a[3]), "r"(b0), "r"(b1));
}
__device__ __forceinline__ void ldsm_x4(uint32_t* d, uint32_t a) {
    asm volatile("ldmatrix.sync.aligned.m8n8.x4.shared.b16 {%0,%1,%2,%3}, [%4];\n"
                 : "=r"(d[0]), "=r"(d[1]), "=r"(d[2]), "=r"(d[3]) : "r"(a));
}
__device__ __forceinline__ void ldsm_x2_t(uint32_t& d0, uint32_t& d1, uint32_t a) {
    asm volatile("ldmatrix.sync.aligned.m8n8.x2.trans.shared.b16 {%0,%1}, [%2];\n"
                 : "=r"(d0), "=r"(d1) : "r"(a));
}
__device__ __forceinline__ uint32_t pack_bf2(__nv_bfloat16 a, __nv_bfloat16 b) {
    __nv_bfloat162 t; t.x = a; t.y = b; return *(uint32_t*)&t;
}

// ---------------- fp32 -> (hi,lo) bf16 split, 4/thread ----------------------
__global__ void __launch_bounds__(256) split4_kernel(
    const float* __restrict__ x, __nv_bfloat16* __restrict__ hi,
    __nv_bfloat16* __restrict__ lo, int n4)
{
    int i = blockIdx.x * 256 + threadIdx.x;
    if (i < n4) {
        float4 v = ((const float4*)x)[i];
        float vs[4] = {v.x, v.y, v.z, v.w};
        __nv_bfloat16 h[4], l[4];
#pragma unroll
        for (int j = 0; j < 4; j++) {
            h[j] = __float2bfloat16(vs[j]);
            l[j] = __float2bfloat16(vs[j] - __bfloat162float(h[j]));
        }
        ((uint2*)hi)[i] = *(uint2*)h;
        ((uint2*)lo)[i] = *(uint2*)l;
    }
}

// ---------------- split-bf16 GEMM, BM=192 x BN=64 ----------------------------
// Y[b,m,p] = sum_c W[m,c]*X[b,c,p].  8 warps = 4m x 2n; acc 48m x 32n per warp.
// A (weights) and B (acts) staged in smem, double-buffered, ldmatrix frags.
// epi: 0 f32 out; 1 silu->f32; 2 (*G)->bf16 hi/lo.
__global__ void __launch_bounds__(256, 2) gemm_bf16_kernel(
    const __nv_bfloat16* __restrict__ Whi, const __nv_bfloat16* __restrict__ Wlo,
    const __nv_bfloat16* __restrict__ Xhi, const __nv_bfloat16* __restrict__ Xlo,
    float* __restrict__ Yf, const float* __restrict__ G,
    __nv_bfloat16* __restrict__ Yhi, __nv_bfloat16* __restrict__ Ylo,
    int M, int epi)
{
    __shared__ __align__(16) __nv_bfloat16 Asm[2][2][192][24]; // [buf][half][m][k+pad]
    __shared__ __align__(16) __nv_bfloat16 Bsm[2][2][16][72];  // [buf][half][k][n+pad]

    const int b  = blockIdx.z;
    const int m0 = blockIdx.y * 192;
    const int n0 = blockIdx.x * 64;
    const size_t xoff = (size_t)b * CC * HWP;

    const int tid  = threadIdx.x;
    const int lane = tid & 31;
    const int warp = tid >> 5;
    const int wm   = (warp >> 1) * 48;     // 0,48,96,144
    const int wn   = (warp & 1) * 32;      // 0,32
    const int gq   = lane >> 2;
    const int tg   = lane & 3;

    // A loader indices: unit u -> row u>>1, k-chunk (u&1)*8 (two uint4 per row)
    const int au0 = tid, au1 = tid + 256;
    // B loader: half = tid>>7, u = tid&127 -> k = u>>3, nc = (u&7)*8
    const int bhf = tid >> 7, bu = tid & 127;
    const int bk = bu >> 3, bnc = (bu & 7) * 8;
    const __nv_bfloat16* Bsrc = bhf ? Xlo : Xhi;

    float acc[3][4][4];
#pragma unroll
    for (int mt = 0; mt < 3; mt++)
#pragma unroll
        for (int nt = 0; nt < 4; nt++)
#pragma unroll
            for (int e = 0; e < 4; e++) acc[mt][nt][e] = 0.f;

    uint4 pa[2][2], pb;
    // prefetch k0 = 0
    {
        const int r0 = au0 >> 1, c0 = (au0 & 1) * 8;
        pa[0][0] = *(const uint4*)(Whi + (size_t)(m0 + r0) * CC + c0);
        pa[0][1] = *(const uint4*)(Wlo + (size_t)(m0 + r0) * CC + c0);
        if (au1 < 384) {
            const int r1 = au1 >> 1, c1 = (au1 & 1) * 8;
            pa[1][0] = *(const uint4*)(Whi + (size_t)(m0 + r1) * CC + c1);
            pa[1][1] = *(const uint4*)(Wlo + (size_t)(m0 + r1) * CC + c1);
        }
        pb = *(const uint4*)(Bsrc + xoff + (size_t)bk * HWP + n0 + bnc);
    }
    // store buf 0
    {
        const int r0 = au0 >> 1, c0 = (au0 & 1) * 8;
        *(uint4*)&Asm[0][0][r0][c0] = pa[0][0];
        *(uint4*)&Asm[0][1][r0][c0] = pa[0][1];
        if (au1 < 384) {
            const int r1 = au1 >> 1, c1 = (au1 & 1) * 8;
            *(uint4*)&Asm[0][0][r1][c1] = pa[1][0];
            *(uint4*)&Asm[0][1][r1][c1] = pa[1][1];
        }
        *(uint4*)&Bsm[0][bhf][bk][bnc] = pb;
    }
    __syncthreads();

    const int NK = CC / 16;
    for (int i = 0; i < NK; i++) {
        const int buf = i & 1;
        if (i + 1 < NK) {
            const int k0 = (i + 1) * 16;
            const int r0 = au0 >> 1, c0 = (au0 & 1) * 8;
            pa[0][0] = *(const uint4*)(Whi + (size_t)(m0 + r0) * CC + k0 + c0);
            pa[0][1] = *(const uint4*)(Wlo + (size_t)(m0 + r0) * CC + k0 + c0);
            if (au1 < 384) {
                const int r1 = au1 >> 1, c1 = (au1 & 1) * 8;
                pa[1][0] = *(const uint4*)(Whi + (size_t)(m0 + r1) * CC + k0 + c1);
                pa[1][1] = *(const uint4*)(Wlo + (size_t)(m0 + r1) * CC + k0 + c1);
            }
            pb = *(const uint4*)(Bsrc + xoff + (size_t)(k0 + bk) * HWP + n0 + bnc);
        }

        // B fragments: [half][nt][2]
        uint32_t bf[2][4][2];
        {
            const uint32_t brow = (uint32_t)(lane & 15) * (72 * 2) + (uint32_t)wn * 2;
            const uint32_t bb0 = smem_u32(&Bsm[buf][0][0][0]) + brow;
            const uint32_t bb1 = smem_u32(&Bsm[buf][1][0][0]) + brow;
#pragma unroll
            for (int nt = 0; nt < 4; nt++) {
                ldsm_x2_t(bf[0][nt][0], bf[0][nt][1], bb0 + nt * 16);
                ldsm_x2_t(bf[1][nt][0], bf[1][nt][1], bb1 + nt * 16);
            }
        }
#pragma unroll
        for (int mt = 0; mt < 3; mt++) {
            uint32_t afh[4], afl[4];
            const int r = wm + mt * 16 + (lane & 15);
            const int cb = (lane >> 4) * 8;
            ldsm_x4(afh, smem_u32(&Asm[buf][0][r][cb]));
            ldsm_x4(afl, smem_u32(&Asm[buf][1][r][cb]));
#pragma unroll
            for (int nt = 0; nt < 4; nt++) {
                mma16816(acc[mt][nt], afh, bf[0][nt][0], bf[0][nt][1]);
                mma16816(acc[mt][nt], afh, bf[1][nt][0], bf[1][nt][1]);
                mma16816(acc[mt][nt], afl, bf[0][nt][0], bf[0][nt][1]);
            }
        }
        if (i + 1 < NK) {
            const int nb = buf ^ 1;
            const int r0 = au0 >> 1, c0 = (au0 & 1) * 8;
            *(uint4*)&Asm[nb][0][r0][c0] = pa[0][0];
            *(uint4*)&Asm[nb][1][r0][c0] = pa[0][1];
            if (au1 < 384) {
                const int r1 = au1 >> 1, c1 = (au1 & 1) * 8;
                *(uint4*)&Asm[nb][0][r1][c1] = pa[1][0];
                *(uint4*)&Asm[nb][1][r1][c1] = pa[1][1];
            }
            *(uint4*)&Bsm[nb][bhf][bk][bnc] = pb;
        }
        __syncthreads();
    }

    // epilogue
    const size_t yoff = (size_t)b * M * HWP;
    const size_t goff = (size_t)b * CC * HWP;
#pragma unroll
    for (int mt = 0; mt < 3; mt++) {
        const int r0 = m0 + wm + mt * 16 + gq;
        const int r1 = r0 + 8;
#pragma unroll
        for (int nt = 0; nt < 4; nt++) {
            const int c = n0 + wn + nt * 8 + 2 * tg;
            float v00 = acc[mt][nt][0], v01 = acc[mt][nt][1];
            float v10 = acc[mt][nt][2], v11 = acc[mt][nt][3];
            if (epi == 1) {
                v00 = v00 / (1.f + __expf(-v00));
                v01 = v01 / (1.f + __expf(-v01));
                v10 = v10 / (1.f + __expf(-v10));
                v11 = v11 / (1.f + __expf(-v11));
            }
            if (epi == 2) {
                float2 g0 = *(const float2*)(G + goff + (size_t)r0 * HWP + c);
                float2 g1 = *(const float2*)(G + goff + (size_t)r1 * HWP + c);
                v00 *= g0.x; v01 *= g0.y; v10 *= g1.x; v11 *= g1.y;
                __nv_bfloat16 h00 = __float2bfloat16(v00);
                __nv_bfloat16 h01 = __float2bfloat16(v01);
                __nv_bfloat16 h10 = __float2bfloat16(v10);
                __nv_bfloat16 h11 = __float2bfloat16(v11);
                *(uint32_t*)(Yhi + yoff + (size_t)r0 * HWP + c) = pack_bf2(h00, h01);
                *(uint32_t*)(Yhi + yoff + (size_t)r1 * HWP + c) = pack_bf2(h10, h11);
                *(uint32_t*)(Ylo + yoff + (size_t)r0 * HWP + c) = pack_bf2(
                    __float2bfloat16(v00 - __bfloat162float(h00)),
                    __float2bfloat16(v01 - __bfloat162float(h01)));
                *(uint32_t*)(Ylo + yoff + (size_t)r1 * HWP + c) = pack_bf2(
                    __float2bfloat16(v10 - __bfloat162float(h10)),
                    __float2bfloat16(v11 - __bfloat162float(h11)));
            } else {
                *(float2*)(Yf + yoff + (size_t)r0 * HWP + c) = make_float2(v00, v01);
                *(float2*)(Yf + yoff + (size_t)r1 * HWP + c) = make_float2(v10, v11);
            }
        }
    }
}

// ---------------- depthwise 3x3, 4 px/thread --------------------------------
__global__ void __launch_bounds__(256) dw_kernel(
    const float* __restrict__ t, const float* __restrict__ wd, float* __restrict__ out)
{
    const int cb = blockIdx.y;
    const int c  = cb % (3 * CC);
    const int p  = (blockIdx.x * 256 + threadIdx.x) * 4;
    const int y  = p >> 8;
    const int x  = p & 255;
    const float* base = t + (size_t)cb * HWP;

    float w[9];
#pragma unroll
    for (int i = 0; i < 9; i++) w[i] = wd[c * 9 + i];

    float a0 = 0.f, a1 = 0.f, a2 = 0.f, a3 = 0.f;
#pragma unroll
    for (int dy = -1; dy <= 1; dy++) {
        const int yy = y + dy;
        if (yy < 0 || yy >= HH) continue;
        const float* r = base + yy * WW + x;
        const float4 f = *(const float4*)r;
        const float left  = (x > 0)   ? r[-1] : 0.f;
        const float right = (x < 252) ? r[4]  : 0.f;
        const float w0 = w[(dy + 1) * 3 + 0];
        const float w1 = w[(dy + 1) * 3 + 1];
        const float w2 = w[(dy + 1) * 3 + 2];
        a0 = fmaf(w0, left, fmaf(w1, f.x, fmaf(w2, f.y, a0)));
        a1 = fmaf(w0, f.x,  fmaf(w1, f.y, fmaf(w2, f.z, a1)));
        a2 = fmaf(w0, f.y,  fmaf(w1, f.z, fmaf(w2, f.w, a2)));
        a3 = fmaf(w0, f.z,  fmaf(w1, f.w, fmaf(w2, right, a3)));
    }
    *(float4*)(out + (size_t)cb * HWP + p) = make_float4(a0, a1, a2, a3);
}

// ---------------- row attention (SIMT, JC=16 — R3 proven) --------------------
#define JC 16

__global__ void __launch_bounds__(256, 2) attn_kernel(
    const float* __restrict__ qkv, const float* __restrict__ rpb,
    __nv_bfloat16* __restrict__ ohi, __nv_bfloat16* __restrict__ olo)
{
    __shared__ float Kc[JC][36];
    __shared__ float Vc[JC][36];
    __shared__ float bsh[512];

    const int row = blockIdx.x, head = blockIdx.y, b = blockIdx.z;
    const int tid = threadIdx.x;
    const size_t base = (((size_t)b * (3 * CC) + head * 32) * HH + row) * WW;
    const size_t koff = (size_t)CC * HWP;
    const size_t voff = 2 * koff;

    for (int i = tid; i < 511; i += 256) bsh[i] = rpb[i * 6 + head];

    float q[32];
#pragma unroll
    for (int d = 0; d < 32; d++) q[d] = qkv[base + (size_t)d * HWP + tid];

    const float scale = 0.17677669529663687f;
    float m = -1e30f, l = 0.f;
    float o[32];
#pragma unroll
    for (int d = 0; d < 32; d++) o[d] = 0.f;

    for (int jt = 0; jt < WW; jt += JC) {
        __syncthreads();
        for (int i = tid; i < JC * 32; i += 256) {
            const int j = i & (JC - 1);
            const int d = i >> 4;
            Kc[j][d] = qkv[base + koff + (size_t)d * HWP + jt + j];
            Vc[j][d] = qkv[base + voff + (size_t)d * HWP + jt + j];
        }
        __syncthreads();

        float s[JC];
#pragma unroll
        for (int jj = 0; jj < JC; jj++) {
            const float4* kp = (const float4*)&Kc[jj][0];
            float acc = 0.f;
#pragma unroll
            for (int c4 = 0; c4 < 8; c4++) {
                float4 kv = kp[c4];
                acc = fmaf(q[c4 * 4 + 0], kv.x, acc);
                acc = fmaf(q[c4 * 4 + 1], kv.y, acc);
                acc = fmaf(q[c4 * 4 + 2], kv.z, acc);
                acc = fmaf(q[c4 * 4 + 3], kv.w, acc);
            }
            s[jj] = acc * scale + bsh[tid - (jt + jj) + 255];
        }
        float mc = m;
#pragma unroll
        for (int jj = 0; jj < JC; jj++) mc = fmaxf(mc, s[jj]);
        const float corr = __expf(m - mc);
        l *= corr;
#pragma unroll
        for (int d = 0; d < 32; d++) o[d] *= corr;
#pragma unroll
        for (int jj = 0; jj < JC; jj++) {
            const float p = __expf(s[jj] - mc);
            l += p;
            const float4* vp = (const float4*)&Vc[jj][0];
#pragma unroll
            for (int c4 = 0; c4 < 8; c4++) {
                float4 vv = vp[c4];
                o[c4 * 4 + 0] = fmaf(p, vv.x, o[c4 * 4 + 0]);
                o[c4 * 4 + 1] = fmaf(p, vv.y, o[c4 * 4 + 1]);
                o[c4 * 4 + 2] = fmaf(p, vv.z, o[c4 * 4 + 2]);
                o[c4 * 4 + 3] = fmaf(p, vv.w, o[c4 * 4 + 3]);
            }
        }
        m = mc;
    }

    const float inv = 1.f / l;
    const size_t obase = (((size_t)b * CC + head * 32) * HH + row) * WW;
#pragma unroll
    for (int d = 0; d < 32; d++) {
        const float v = o[d] * inv;
        __nv_bfloat16 h = __float2bfloat16(v);
        ohi[obase + (size_t)d * HWP + tid] = h;
        olo[obase + (size_t)d * HWP + tid] = __float2bfloat16(v - __bfloat162float(h));
    }
}

// ---------------- launch ------------------------------------------------------
extern "C" void kernel_launch(void* const* d_in, const int* in_sizes, int n_in,
                              void* d_out, int out_size)
{
    const float* x       = (const float*)d_in[0];
    const float* rpb     = (const float*)d_in[1];
    const float* w_qkv   = (const float*)d_in[2];
    const float* w_depth = (const float*)d_in[3];
    const float* w_pre   = (const float*)d_in[4];
    const float* w_out   = (const float*)d_in[5];
    const float* w_gate  = (const float*)d_in[6];
    float* out = (float*)d_out;
    (void)in_sizes; (void)n_in; (void)out_size;

    float *gate, *t, *qkv;
    __nv_bfloat16 *xhi, *xlo, *ahi, *alo, *yhi, *ylo, *whi, *wlo;
    cudaGetSymbolAddress((void**)&gate, g_gate);
    cudaGetSymbolAddress((void**)&t,    g_t);
    cudaGetSymbolAddress((void**)&qkv,  g_qkv);
    cudaGetSymbolAddress((void**)&xhi,  g_xhi);
    cudaGetSymbolAddress((void**)&xlo,  g_xlo);
    cudaGetSymbolAddress((void**)&ahi,  g_ahi);
    cudaGetSymbolAddress((void**)&alo,  g_alo);
    cudaGetSymbolAddress((void**)&yhi,  g_yhi);
    cudaGetSymbolAddress((void**)&ylo,  g_ylo);
    cudaGetSymbolAddress((void**)&whi,  g_whi);
    cudaGetSymbolAddress((void**)&wlo,  g_wlo);

    const int WQ = 3 * CC * CC;
    const int WS = CC * CC;
    split4_kernel<<<(WQ / 4 + 255) / 256, 256>>>(w_qkv,  whi,          wlo,          WQ / 4);
    split4_kernel<<<(WS / 4 + 255) / 256, 256>>>(w_pre,  whi + 3 * WS, wlo + 3 * WS, WS / 4);
    split4_kernel<<<(WS / 4 + 255) / 256, 256>>>(w_out,  whi + 4 * WS, wlo + 4 * WS, WS / 4);
    split4_kernel<<<(WS / 4 + 255) / 256, 256>>>(w_gate, whi + 5 * WS, wlo + 5 * WS, WS / 4);

    const int nx = NB * CC * HWP;
    split4_kernel<<<(nx / 4 + 255) / 256, 256>>>(x, xhi, xlo, nx / 4);

    const dim3 gSmall(HWP / 64, 1, NB);      // (512, 1, 2)
    const dim3 gQkv(HWP / 64, 3, NB);        // (512, 3, 2)

    gemm_bf16_kernel<<<gSmall, 256>>>(whi + 5 * WS, wlo + 5 * WS, xhi, xlo,
                                      gate, nullptr, nullptr, nullptr, CC, 1);
    gemm_bf16_kernel<<<gQkv, 256>>>(whi, wlo, xhi, xlo,
                                    t, nullptr, nullptr, nullptr, 3 * CC, 0);
    dw_kernel<<<dim3(HWP / 1024, NB * 3 * CC), 256>>>(t, w_depth, qkv);
    attn_kernel<<<dim3(HH, 6, NB), 256>>>(qkv, rpb, ahi, alo);
    gemm_bf16_kernel<<<gSmall, 256>>>(whi + 3 * WS, wlo + 3 * WS, ahi, alo,
                                      nullptr, gate, yhi, ylo, CC, 2);
    gemm_bf16_kernel<<<gSmall, 256>>>(whi + 4 * WS, wlo + 4 * WS, yhi, ylo,
                                      out, nullptr, nullptr, nullptr, CC, 0);
}

// round 7
// speedup vs baseline: 1.9098x; 1.4502x over previous
#include <cuda_runtime.h>
#include <cuda_bf16.h>
#include <math.h>
#include <stdint.h>

#define HH 128
#define WW 256
#define CC 192
#define HWP (128*256)
#define NB 2
#define LOG2E 1.4426950408889634f

// ---------------- scratch (device globals) ----------------------------------
__device__ float g_gate[NB * CC * HWP];
__device__ float g_t[NB * 3 * CC * HWP];
__device__ float g_qkv[NB * 3 * CC * HWP];   // reused as bf16 hi|lo halves
__device__ __nv_bfloat16 g_xhi[NB * CC * HWP];
__device__ __nv_bfloat16 g_xlo[NB * CC * HWP];
__device__ __nv_bfloat16 g_ahi[NB * CC * HWP];
__device__ __nv_bfloat16 g_alo[NB * CC * HWP];
__device__ __nv_bfloat16 g_yhi[NB * CC * HWP];
__device__ __nv_bfloat16 g_ylo[NB * CC * HWP];
__device__ __nv_bfloat16 g_whi[6 * CC * CC];
__device__ __nv_bfloat16 g_wlo[6 * CC * CC];

// ---------------- helpers -----------------------------------------------------
__device__ __forceinline__ uint32_t smem_u32(const void* p) {
    uint32_t a;
    asm("{ .reg .u64 t; cvta.to.shared.u64 t, %1; cvt.u32.u64 %0, t; }" : "=r"(a) : "l"(p));
    return a;
}
__device__ __forceinline__ void mma16816(float* c, const uint32_t* a,
                                         uint32_t b0, uint32_t b1)
{
    asm volatile(
        "mma.sync.aligned.m16n8k16.row.col.f32.bf16.bf16.f32 "
        "{%0,%1,%2,%3}, {%4,%5,%6,%7}, {%8,%9}, {%0,%1,%2,%3};\n"
        : "+f"(c[0]), "+f"(c[1]), "+f"(c[2]), "+f"(c[3])
        : "r"(a[0]), "r"(a[1]), "r"(a[2]), "r"(a[3]), "r"(b0), "r"(b1));
}
__device__ __forceinline__ void ldsm_x4(uint32_t* d, uint32_t a) {
    asm volatile("ldmatrix.sync.aligned.m8n8.x4.shared.b16 {%0,%1,%2,%3}, [%4];\n"
                 : "=r"(d[0]), "=r"(d[1]), "=r"(d[2]), "=r"(d[3]) : "r"(a));
}
__device__ __forceinline__ void ldsm_x4_t(uint32_t* d, uint32_t a) {
    asm volatile("ldmatrix.sync.aligned.m8n8.x4.trans.shared.b16 {%0,%1,%2,%3}, [%4];\n"
                 : "=r"(d[0]), "=r"(d[1]), "=r"(d[2]), "=r"(d[3]) : "r"(a));
}
__device__ __forceinline__ void ldsm_x2(uint32_t& d0, uint32_t& d1, uint32_t a) {
    asm volatile("ldmatrix.sync.aligned.m8n8.x2.shared.b16 {%0,%1}, [%2];\n"
                 : "=r"(d0), "=r"(d1) : "r"(a));
}
__device__ __forceinline__ void ldsm_x2_t(uint32_t& d0, uint32_t& d1, uint32_t a) {
    asm volatile("ldmatrix.sync.aligned.m8n8.x2.trans.shared.b16 {%0,%1}, [%2];\n"
                 : "=r"(d0), "=r"(d1) : "r"(a));
}
__device__ __forceinline__ uint32_t pack_bf2(__nv_bfloat16 a, __nv_bfloat16 b) {
    __nv_bfloat162 t; t.x = a; t.y = b; return *(uint32_t*)&t;
}

// ---------------- fp32 -> (hi,lo) bf16 split, 4/thread ----------------------
__global__ void __launch_bounds__(256) split4_kernel(
    const float* __restrict__ x, __nv_bfloat16* __restrict__ hi,
    __nv_bfloat16* __restrict__ lo, int n4)
{
    int i = blockIdx.x * 256 + threadIdx.x;
    if (i < n4) {
        float4 v = ((const float4*)x)[i];
        float vs[4] = {v.x, v.y, v.z, v.w};
        __nv_bfloat16 h[4], l[4];
#pragma unroll
        for (int j = 0; j < 4; j++) {
            h[j] = __float2bfloat16(vs[j]);
            l[j] = __float2bfloat16(vs[j] - __bfloat162float(h[j]));
        }
        ((uint2*)hi)[i] = *(uint2*)h;
        ((uint2*)lo)[i] = *(uint2*)l;
    }
}

// ---------------- split-bf16 GEMM, BM=192 x BN=64 (R6, proven) ---------------
__global__ void __launch_bounds__(256, 2) gemm_bf16_kernel(
    const __nv_bfloat16* __restrict__ Whi, const __nv_bfloat16* __restrict__ Wlo,
    const __nv_bfloat16* __restrict__ Xhi, const __nv_bfloat16* __restrict__ Xlo,
    float* __restrict__ Yf, const float* __restrict__ G,
    __nv_bfloat16* __restrict__ Yhi, __nv_bfloat16* __restrict__ Ylo,
    int M, int epi)
{
    __shared__ __align__(16) __nv_bfloat16 Asm[2][2][192][24];
    __shared__ __align__(16) __nv_bfloat16 Bsm[2][2][16][72];

    const int b  = blockIdx.z;
    const int m0 = blockIdx.y * 192;
    const int n0 = blockIdx.x * 64;
    const size_t xoff = (size_t)b * CC * HWP;

    const int tid  = threadIdx.x;
    const int lane = tid & 31;
    const int warp = tid >> 5;
    const int wm   = (warp >> 1) * 48;
    const int wn   = (warp & 1) * 32;
    const int gq   = lane >> 2;
    const int tg   = lane & 3;

    const int au0 = tid, au1 = tid + 256;
    const int bhf = tid >> 7, bu = tid & 127;
    const int bk = bu >> 3, bnc = (bu & 7) * 8;
    const __nv_bfloat16* Bsrc = bhf ? Xlo : Xhi;

    float acc[3][4][4];
#pragma unroll
    for (int mt = 0; mt < 3; mt++)
#pragma unroll
        for (int nt = 0; nt < 4; nt++)
#pragma unroll
            for (int e = 0; e < 4; e++) acc[mt][nt][e] = 0.f;

    uint4 pa[2][2], pb;
    {
        const int r0 = au0 >> 1, c0 = (au0 & 1) * 8;
        pa[0][0] = *(const uint4*)(Whi + (size_t)(m0 + r0) * CC + c0);
        pa[0][1] = *(const uint4*)(Wlo + (size_t)(m0 + r0) * CC + c0);
        if (au1 < 384) {
            const int r1 = au1 >> 1, c1 = (au1 & 1) * 8;
            pa[1][0] = *(const uint4*)(Whi + (size_t)(m0 + r1) * CC + c1);
            pa[1][1] = *(const uint4*)(Wlo + (size_t)(m0 + r1) * CC + c1);
        }
        pb = *(const uint4*)(Bsrc + xoff + (size_t)bk * HWP + n0 + bnc);
    }
    {
        const int r0 = au0 >> 1, c0 = (au0 & 1) * 8;
        *(uint4*)&Asm[0][0][r0][c0] = pa[0][0];
        *(uint4*)&Asm[0][1][r0][c0] = pa[0][1];
        if (au1 < 384) {
            const int r1 = au1 >> 1, c1 = (au1 & 1) * 8;
            *(uint4*)&Asm[0][0][r1][c1] = pa[1][0];
            *(uint4*)&Asm[0][1][r1][c1] = pa[1][1];
        }
        *(uint4*)&Bsm[0][bhf][bk][bnc] = pb;
    }
    __syncthreads();

    const int NK = CC / 16;
    for (int i = 0; i < NK; i++) {
        const int buf = i & 1;
        if (i + 1 < NK) {
            const int k0 = (i + 1) * 16;
            const int r0 = au0 >> 1, c0 = (au0 & 1) * 8;
            pa[0][0] = *(const uint4*)(Whi + (size_t)(m0 + r0) * CC + k0 + c0);
            pa[0][1] = *(const uint4*)(Wlo + (size_t)(m0 + r0) * CC + k0 + c0);
            if (au1 < 384) {
                const int r1 = au1 >> 1, c1 = (au1 & 1) * 8;
                pa[1][0] = *(const uint4*)(Whi + (size_t)(m0 + r1) * CC + k0 + c1);
                pa[1][1] = *(const uint4*)(Wlo + (size_t)(m0 + r1) * CC + k0 + c1);
            }
            pb = *(const uint4*)(Bsrc + xoff + (size_t)(k0 + bk) * HWP + n0 + bnc);
        }
        uint32_t bf[2][4][2];
        {
            const uint32_t brow = (uint32_t)(lane & 15) * (72 * 2) + (uint32_t)wn * 2;
            const uint32_t bb0 = smem_u32(&Bsm[buf][0][0][0]) + brow;
            const uint32_t bb1 = smem_u32(&Bsm[buf][1][0][0]) + brow;
#pragma unroll
            for (int nt = 0; nt < 4; nt++) {
                ldsm_x2_t(bf[0][nt][0], bf[0][nt][1], bb0 + nt * 16);
                ldsm_x2_t(bf[1][nt][0], bf[1][nt][1], bb1 + nt * 16);
            }
        }
#pragma unroll
        for (int mt = 0; mt < 3; mt++) {
            uint32_t afh[4], afl[4];
            const int r = wm + mt * 16 + (lane & 15);
            const int cb = (lane >> 4) * 8;
            ldsm_x4(afh, smem_u32(&Asm[buf][0][r][cb]));
            ldsm_x4(afl, smem_u32(&Asm[buf][1][r][cb]));
#pragma unroll
            for (int nt = 0; nt < 4; nt++) {
                mma16816(acc[mt][nt], afh, bf[0][nt][0], bf[0][nt][1]);
                mma16816(acc[mt][nt], afh, bf[1][nt][0], bf[1][nt][1]);
                mma16816(acc[mt][nt], afl, bf[0][nt][0], bf[0][nt][1]);
            }
        }
        if (i + 1 < NK) {
            const int nb = buf ^ 1;
            const int r0 = au0 >> 1, c0 = (au0 & 1) * 8;
            *(uint4*)&Asm[nb][0][r0][c0] = pa[0][0];
            *(uint4*)&Asm[nb][1][r0][c0] = pa[0][1];
            if (au1 < 384) {
                const int r1 = au1 >> 1, c1 = (au1 & 1) * 8;
                *(uint4*)&Asm[nb][0][r1][c1] = pa[1][0];
                *(uint4*)&Asm[nb][1][r1][c1] = pa[1][1];
            }
            *(uint4*)&Bsm[nb][bhf][bk][bnc] = pb;
        }
        __syncthreads();
    }

    const size_t yoff = (size_t)b * M * HWP;
    const size_t goff = (size_t)b * CC * HWP;
#pragma unroll
    for (int mt = 0; mt < 3; mt++) {
        const int r0 = m0 + wm + mt * 16 + gq;
        const int r1 = r0 + 8;
#pragma unroll
        for (int nt = 0; nt < 4; nt++) {
            const int c = n0 + wn + nt * 8 + 2 * tg;
            float v00 = acc[mt][nt][0], v01 = acc[mt][nt][1];
            float v10 = acc[mt][nt][2], v11 = acc[mt][nt][3];
            if (epi == 1) {
                v00 = v00 / (1.f + __expf(-v00));
                v01 = v01 / (1.f + __expf(-v01));
                v10 = v10 / (1.f + __expf(-v10));
                v11 = v11 / (1.f + __expf(-v11));
            }
            if (epi == 2) {
                float2 g0 = *(const float2*)(G + goff + (size_t)r0 * HWP + c);
                float2 g1 = *(const float2*)(G + goff + (size_t)r1 * HWP + c);
                v00 *= g0.x; v01 *= g0.y; v10 *= g1.x; v11 *= g1.y;
                __nv_bfloat16 h00 = __float2bfloat16(v00);
                __nv_bfloat16 h01 = __float2bfloat16(v01);
                __nv_bfloat16 h10 = __float2bfloat16(v10);
                __nv_bfloat16 h11 = __float2bfloat16(v11);
                *(uint32_t*)(Yhi + yoff + (size_t)r0 * HWP + c) = pack_bf2(h00, h01);
                *(uint32_t*)(Yhi + yoff + (size_t)r1 * HWP + c) = pack_bf2(h10, h11);
                *(uint32_t*)(Ylo + yoff + (size_t)r0 * HWP + c) = pack_bf2(
                    __float2bfloat16(v00 - __bfloat162float(h00)),
                    __float2bfloat16(v01 - __bfloat162float(h01)));
                *(uint32_t*)(Ylo + yoff + (size_t)r1 * HWP + c) = pack_bf2(
                    __float2bfloat16(v10 - __bfloat162float(h10)),
                    __float2bfloat16(v11 - __bfloat162float(h11)));
            } else {
                *(float2*)(Yf + yoff + (size_t)r0 * HWP + c) = make_float2(v00, v01);
                *(float2*)(Yf + yoff + (size_t)r1 * HWP + c) = make_float2(v10, v11);
            }
        }
    }
}

// ---------------- depthwise 3x3 -> split bf16 hi/lo --------------------------
__global__ void __launch_bounds__(256) dw_kernel(
    const float* __restrict__ t, const float* __restrict__ wd,
    __nv_bfloat16* __restrict__ oh, __nv_bfloat16* __restrict__ ol)
{
    const int cb = blockIdx.y;
    const int c  = cb % (3 * CC);
    const int p  = (blockIdx.x * 256 + threadIdx.x) * 4;
    const int y  = p >> 8;
    const int x  = p & 255;
    const float* base = t + (size_t)cb * HWP;

    float w[9];
#pragma unroll
    for (int i = 0; i < 9; i++) w[i] = wd[c * 9 + i];

    float a[4] = {0.f, 0.f, 0.f, 0.f};
#pragma unroll
    for (int dy = -1; dy <= 1; dy++) {
        const int yy = y + dy;
        if (yy < 0 || yy >= HH) continue;
        const float* r = base + yy * WW + x;
        const float4 f = *(const float4*)r;
        const float left  = (x > 0)   ? r[-1] : 0.f;
        const float right = (x < 252) ? r[4]  : 0.f;
        const float w0 = w[(dy + 1) * 3 + 0];
        const float w1 = w[(dy + 1) * 3 + 1];
        const float w2 = w[(dy + 1) * 3 + 2];
        a[0] = fmaf(w0, left, fmaf(w1, f.x, fmaf(w2, f.y, a[0])));
        a[1] = fmaf(w0, f.x,  fmaf(w1, f.y, fmaf(w2, f.z, a[1])));
        a[2] = fmaf(w0, f.y,  fmaf(w1, f.z, fmaf(w2, f.w, a[2])));
        a[3] = fmaf(w0, f.z,  fmaf(w1, f.w, fmaf(w2, right, a[3])));
    }
    __nv_bfloat16 h[4], l[4];
#pragma unroll
    for (int i = 0; i < 4; i++) {
        h[i] = __float2bfloat16(a[i]);
        l[i] = __float2bfloat16(a[i] - __bfloat162float(h[i]));
    }
    *(uint2*)(oh + (size_t)cb * HWP + p) = *(uint2*)h;
    *(uint2*)(ol + (size_t)cb * HWP + p) = *(uint2*)l;
}

// ---------------- attention via mma.sync v2 ----------------------------------
// block = (row, qhalf*head, b); 8 warps x 16 queries = 128 queries/block.
// K/V pre-split bf16 in gmem; chunk = 64 keys; natural [d][j] smem layout.
__global__ void __launch_bounds__(256, 2) attn_mma_kernel(
    const __nv_bfloat16* __restrict__ qvh, const __nv_bfloat16* __restrict__ qvl,
    const float* __restrict__ rpb,
    __nv_bfloat16* __restrict__ ohi, __nv_bfloat16* __restrict__ olo)
{
    __shared__ float bsh[512];
    __shared__ __align__(16) __nv_bfloat16 KV[4][32][72];  // Kh,Kl,Vh,Vl [d][j]

    const int row = blockIdx.x;
    const int head = blockIdx.y % 6, qh = blockIdx.y / 6;
    const int b = blockIdx.z;
    const int tid = threadIdx.x, lane = tid & 31, warp = tid >> 5;
    const int gq = lane >> 2, tg = lane & 3;
    const size_t base = (((size_t)b * (3 * CC) + head * 32) * HH + row) * WW;
    const size_t koff = (size_t)CC * HWP;
    const float scale2 = 0.17677669529663687f * LOG2E;

    for (int i = tid; i < 511; i += 256) bsh[i] = rpb[i * 6 + head] * LOG2E;

    // ---- stage Q (hi then lo) through KV area, build A fragments ----
    uint32_t qf[2][2][4];
    {
        __nv_bfloat16* Qst = &KV[0][0][0];    // [32][136]
        const int d = tid >> 3, q16 = (tid & 7) * 16;
        const int lrow = ((lane >> 4) & 1) * 8 + (lane & 7);
        const int lcol = warp * 16 + ((lane >> 3) & 1) * 8;
#pragma unroll
        for (int h = 0; h < 2; h++) {
            const __nv_bfloat16* src = h ? qvl : qvh;
            const size_t go = base + (size_t)d * HWP + qh * 128 + q16;
            uint4 v0 = *(const uint4*)(src + go);
            uint4 v1 = *(const uint4*)(src + go + 8);
            __syncthreads();
            *(uint4*)&Qst[d * 136 + q16] = v0;
            *(uint4*)&Qst[d * 136 + q16 + 8] = v1;
            __syncthreads();
#pragma unroll
            for (int ks = 0; ks < 2; ks++)
                ldsm_x4_t(qf[h][ks], smem_u32(&Qst[(ks * 16 + lrow) * 136 + lcol]));
        }
    }

    float m2[2] = {-1e30f, -1e30f}, l2[2] = {0.f, 0.f};
    float o[4][4];
#pragma unroll
    for (int nt = 0; nt < 4; nt++)
#pragma unroll
        for (int e = 0; e < 4; e++) o[nt][e] = 0.f;

    const int cd = tid >> 3, cj = (tid & 7) * 8;     // chunk copy indices
    for (int jt = 0; jt < WW; jt += 64) {
        const size_t kb = base + koff + (size_t)cd * HWP + jt + cj;
        uint4 r0 = *(const uint4*)(qvh + kb);
        uint4 r1 = *(const uint4*)(qvl + kb);
        uint4 r2 = *(const uint4*)(qvh + kb + koff);
        uint4 r3 = *(const uint4*)(qvl + kb + koff);
        __syncthreads();
        *(uint4*)&KV[0][cd][cj] = r0;
        *(uint4*)&KV[1][cd][cj] = r1;
        *(uint4*)&KV[2][cd][cj] = r2;
        *(uint4*)&KV[3][cd][cj] = r3;
        __syncthreads();

        // ---- S = Q K^T ----
        float s[8][4];
#pragma unroll
        for (int nt = 0; nt < 8; nt++)
#pragma unroll
            for (int e = 0; e < 4; e++) s[nt][e] = 0.f;
        const int krow = lane & 15;
#pragma unroll
        for (int ks = 0; ks < 2; ks++) {
            const uint32_t kb0 = smem_u32(&KV[0][ks * 16 + krow][0]);
            const uint32_t kb1 = smem_u32(&KV[1][ks * 16 + krow][0]);
#pragma unroll
            for (int nt = 0; nt < 8; nt++) {
                uint32_t h0, h1, l0, l1;
                ldsm_x2_t(h0, h1, kb0 + nt * 16);
                ldsm_x2_t(l0, l1, kb1 + nt * 16);
                mma16816(s[nt], qf[0][ks], h0, h1);
                mma16816(s[nt], qf[0][ks], l0, l1);
                mma16816(s[nt], qf[1][ks], h0, h1);
            }
        }

        // ---- bias + max (log2 domain) ----
        float mx[2] = {m2[0], m2[1]};
        const int i0 = qh * 128 + warp * 16 + gq;
#pragma unroll
        for (int nt = 0; nt < 8; nt++) {
            const int jb = jt + nt * 8 + 2 * tg;
#pragma unroll
            for (int e = 0; e < 4; e++) {
                const int i = i0 + (e >> 1) * 8;
                const int j = jb + (e & 1);
                const float t = fmaf(s[nt][e], scale2, bsh[i - j + 255]);
                s[nt][e] = t;
                mx[e >> 1] = fmaxf(mx[e >> 1], t);
            }
        }
#pragma unroll
        for (int sl = 0; sl < 2; sl++) {
            float v = mx[sl];
            v = fmaxf(v, __shfl_xor_sync(0xFFFFFFFFu, v, 1));
            v = fmaxf(v, __shfl_xor_sync(0xFFFFFFFFu, v, 2));
            mx[sl] = v;
        }
        float cf[2];
#pragma unroll
        for (int sl = 0; sl < 2; sl++) {
            cf[sl] = exp2f(m2[sl] - mx[sl]);
            m2[sl] = mx[sl];
            l2[sl] *= cf[sl];
        }
#pragma unroll
        for (int nt = 0; nt < 4; nt++)
#pragma unroll
            for (int e = 0; e < 4; e++) o[nt][e] *= cf[e >> 1];

        // ---- P = exp2(S - m); PV ----
        float rs[2] = {0.f, 0.f};
#pragma unroll
        for (int kp = 0; kp < 4; kp++) {
            uint32_t pfh[4], pfl[4];
#pragma unroll
            for (int h2 = 0; h2 < 2; h2++) {
                const int nt = 2 * kp + h2;
                float p0 = exp2f(s[nt][0] - m2[0]);
                float p1 = exp2f(s[nt][1] - m2[0]);
                float p2 = exp2f(s[nt][2] - m2[1]);
                float p3 = exp2f(s[nt][3] - m2[1]);
                rs[0] += p0 + p1;
                rs[1] += p2 + p3;
                __nv_bfloat16 h0 = __float2bfloat16(p0);
                __nv_bfloat16 h1 = __float2bfloat16(p1);
                __nv_bfloat16 h2b = __float2bfloat16(p2);
                __nv_bfloat16 h3 = __float2bfloat16(p3);
                pfh[h2 * 2 + 0] = pack_bf2(h0, h1);
                pfh[h2 * 2 + 1] = pack_bf2(h2b, h3);
                pfl[h2 * 2 + 0] = pack_bf2(
                    __float2bfloat16(p0 - __bfloat162float(h0)),
                    __float2bfloat16(p1 - __bfloat162float(h1)));
                pfl[h2 * 2 + 1] = pack_bf2(
                    __float2bfloat16(p2 - __bfloat162float(h2b)),
                    __float2bfloat16(p3 - __bfloat162float(h3)));
            }
            const int vr = lane & 7, vk = kp * 16 + ((lane >> 3) & 1) * 8;
#pragma unroll
            for (int ntv = 0; ntv < 4; ntv++) {
                uint32_t vh0, vh1, vl0, vl1;
                ldsm_x2(vh0, vh1, smem_u32(&KV[2][ntv * 8 + vr][vk]));
                ldsm_x2(vl0, vl1, smem_u32(&KV[3][ntv * 8 + vr][vk]));
                mma16816(o[ntv], pfh, vh0, vh1);
                mma16816(o[ntv], pfh, vl0, vl1);
                mma16816(o[ntv], pfl, vh0, vh1);
            }
        }
#pragma unroll
        for (int sl = 0; sl < 2; sl++) {
            float r = rs[sl];
            r += __shfl_xor_sync(0xFFFFFFFFu, r, 1);
            r += __shfl_xor_sync(0xFFFFFFFFu, r, 2);
            l2[sl] += r;
        }
    }

    // ---- epilogue: normalize -> smem [q][d] -> coalesced split store ----
    __syncthreads();
    float* stage = (float*)&KV[0][0][0];   // [128][33]
    const float inv0 = 1.f / l2[0], inv1 = 1.f / l2[1];
#pragma unroll
    for (int nt = 0; nt < 4; nt++) {
        const int c = nt * 8 + 2 * tg;
#pragma unroll
        for (int e = 0; e < 4; e++) {
            const int rr = warp * 16 + gq + (e >> 1) * 8;
            stage[rr * 33 + c + (e & 1)] = o[nt][e] * ((e >> 1) ? inv1 : inv0);
        }
    }
    __syncthreads();
    const size_t obase = (((size_t)b * CC + head * 32) * HH + row) * WW + qh * 128;
    const int q = tid & 127, db = (tid >> 7) * 16;
#pragma unroll
    for (int dd = 0; dd < 16; dd++) {
        const int d = db + dd;
        const float v = stage[q * 33 + d];
        __nv_bfloat16 h = __float2bfloat16(v);
        ohi[obase + (size_t)d * HWP + q] = h;
        olo[obase + (size_t)d * HWP + q] = __float2bfloat16(v - __bfloat162float(h));
    }
}

// ---------------- launch ------------------------------------------------------
extern "C" void kernel_launch(void* const* d_in, const int* in_sizes, int n_in,
                              void* d_out, int out_size)
{
    const float* x       = (const float*)d_in[0];
    const float* rpb     = (const float*)d_in[1];
    const float* w_qkv   = (const float*)d_in[2];
    const float* w_depth = (const float*)d_in[3];
    const float* w_pre   = (const float*)d_in[4];
    const float* w_out   = (const float*)d_in[5];
    const float* w_gate  = (const float*)d_in[6];
    float* out = (float*)d_out;
    (void)in_sizes; (void)n_in; (void)out_size;

    float *gate, *t, *qkvf;
    __nv_bfloat16 *xhi, *xlo, *ahi, *alo, *yhi, *ylo, *whi, *wlo;
    cudaGetSymbolAddress((void**)&gate, g_gate);
    cudaGetSymbolAddress((void**)&t,    g_t);
    cudaGetSymbolAddress((void**)&qkvf, g_qkv);
    cudaGetSymbolAddress((void**)&xhi,  g_xhi);
    cudaGetSymbolAddress((void**)&xlo,  g_xlo);
    cudaGetSymbolAddress((void**)&ahi,  g_ahi);
    cudaGetSymbolAddress((void**)&alo,  g_alo);
    cudaGetSymbolAddress((void**)&yhi,  g_yhi);
    cudaGetSymbolAddress((void**)&ylo,  g_ylo);
    cudaGetSymbolAddress((void**)&whi,  g_whi);
    cudaGetSymbolAddress((void**)&wlo,  g_wlo);
    __nv_bfloat16* qvh = (__nv_bfloat16*)qkvf;
    __nv_bfloat16* qvl = qvh + (size_t)NB * 3 * CC * HWP;

    const int WQ = 3 * CC * CC;
    const int WS = CC * CC;
    split4_kernel<<<(WQ / 4 + 255) / 256, 256>>>(w_qkv,  whi,          wlo,          WQ / 4);
    split4_kernel<<<(WS / 4 + 255) / 256, 256>>>(w_pre,  whi + 3 * WS, wlo + 3 * WS, WS / 4);
    split4_kernel<<<(WS / 4 + 255) / 256, 256>>>(w_out,  whi + 4 * WS, wlo + 4 * WS, WS / 4);
    split4_kernel<<<(WS / 4 + 255) / 256, 256>>>(w_gate, whi + 5 * WS, wlo + 5 * WS, WS / 4);

    const int nx = NB * CC * HWP;
    split4_kernel<<<(nx / 4 + 255) / 256, 256>>>(x, xhi, xlo, nx / 4);

    const dim3 gSmall(HWP / 64, 1, NB);
    const dim3 gQkv(HWP / 64, 3, NB);

    gemm_bf16_kernel<<<gSmall, 256>>>(whi + 5 * WS, wlo + 5 * WS, xhi, xlo,
                                      gate, nullptr, nullptr, nullptr, CC, 1);
    gemm_bf16_kernel<<<gQkv, 256>>>(whi, wlo, xhi, xlo,
                                    t, nullptr, nullptr, nullptr, 3 * CC, 0);
    dw_kernel<<<dim3(HWP / 1024, NB * 3 * CC), 256>>>(t, w_depth, qvh, qvl);
    attn_mma_kernel<<<dim3(HH, 12, NB), 256>>>(qvh, qvl, rpb, ahi, alo);
    gemm_bf16_kernel<<<gSmall, 256>>>(whi + 3 * WS, wlo + 3 * WS, ahi, alo,
                                      nullptr, gate, yhi, ylo, CC, 2);
    gemm_bf16_kernel<<<gSmall, 256>>>(whi + 4 * WS, wlo + 4 * WS, yhi, ylo,
                                      out, nullptr, nullptr, nullptr, CC, 0);
}

// round 8
// speedup vs baseline: 1.9336x; 1.0125x over previous
#include <cuda_runtime.h>
#include <cuda_bf16.h>
#include <math.h>
#include <stdint.h>

#define HH 128
#define WW 256
#define CC 192
#define HWP (128*256)
#define NB 2
#define LOG2E 1.4426950408889634f

// ---------------- scratch (device globals) ----------------------------------
__device__ float g_gate[NB * CC * HWP];
__device__ float g_t[NB * 3 * CC * HWP];
__device__ float g_qkv[NB * 3 * CC * HWP];   // reused as bf16 hi|lo halves
__device__ __nv_bfloat16 g_xhi[NB * CC * HWP];
__device__ __nv_bfloat16 g_xlo[NB * CC * HWP];
__device__ __nv_bfloat16 g_ahi[NB * CC * HWP];
__device__ __nv_bfloat16 g_alo[NB * CC * HWP];
__device__ __nv_bfloat16 g_yhi[NB * CC * HWP];
__device__ __nv_bfloat16 g_ylo[NB * CC * HWP];
__device__ __nv_bfloat16 g_whi[6 * CC * CC];
__device__ __nv_bfloat16 g_wlo[6 * CC * CC];

// ---------------- helpers -----------------------------------------------------
__device__ __forceinline__ uint32_t smem_u32(const void* p) {
    uint32_t a;
    asm("{ .reg .u64 t; cvta.to.shared.u64 t, %1; cvt.u32.u64 %0, t; }" : "=r"(a) : "l"(p));
    return a;
}
__device__ __forceinline__ void mma16816(float* c, const uint32_t* a,
                                         uint32_t b0, uint32_t b1)
{
    asm volatile(
        "mma.sync.aligned.m16n8k16.row.col.f32.bf16.bf16.f32 "
        "{%0,%1,%2,%3}, {%4,%5,%6,%7}, {%8,%9}, {%0,%1,%2,%3};\n"
        : "+f"(c[0]), "+f"(c[1]), "+f"(c[2]), "+f"(c[3])
        : "r"(a[0]), "r"(a[1]), "r"(a[2]), "r"(a[3]), "r"(b0), "r"(b1));
}
__device__ __forceinline__ void ldsm_x4(uint32_t* d, uint32_t a) {
    asm volatile("ldmatrix.sync.aligned.m8n8.x4.shared.b16 {%0,%1,%2,%3}, [%4];\n"
                 : "=r"(d[0]), "=r"(d[1]), "=r"(d[2]), "=r"(d[3]) : "r"(a));
}
__device__ __forceinline__ void ldsm_x4_t(uint32_t* d, uint32_t a) {
    asm volatile("ldmatrix.sync.aligned.m8n8.x4.trans.shared.b16 {%0,%1,%2,%3}, [%4];\n"
                 : "=r"(d[0]), "=r"(d[1]), "=r"(d[2]), "=r"(d[3]) : "r"(a));
}
__device__ __forceinline__ void ldsm_x2(uint32_t& d0, uint32_t& d1, uint32_t a) {
    asm volatile("ldmatrix.sync.aligned.m8n8.x2.shared.b16 {%0,%1}, [%2];\n"
                 : "=r"(d0), "=r"(d1) : "r"(a));
}
__device__ __forceinline__ void ldsm_x2_t(uint32_t& d0, uint32_t& d1, uint32_t a) {
    asm volatile("ldmatrix.sync.aligned.m8n8.x2.trans.shared.b16 {%0,%1}, [%2];\n"
                 : "=r"(d0), "=r"(d1) : "r"(a));
}
__device__ __forceinline__ uint32_t pack_bf2(__nv_bfloat16 a, __nv_bfloat16 b) {
    __nv_bfloat162 t; t.x = a; t.y = b; return *(uint32_t*)&t;
}
#define CP_CA(d, s) asm volatile("cp.async.ca.shared.global [%0], [%1], 16;\n" :: "r"(d), "l"(s))
#define CP_CG(d, s) asm volatile("cp.async.cg.shared.global [%0], [%1], 16;\n" :: "r"(d), "l"(s))
#define CP_COMMIT() asm volatile("cp.async.commit_group;\n" ::: "memory")
#define CP_WAIT2()  asm volatile("cp.async.wait_group 2;\n" ::: "memory")

// ---------------- fp32 -> (hi,lo) bf16 split, 4/thread ----------------------
__global__ void __launch_bounds__(256) split4_kernel(
    const float* __restrict__ x, __nv_bfloat16* __restrict__ hi,
    __nv_bfloat16* __restrict__ lo, int n4)
{
    int i = blockIdx.x * 256 + threadIdx.x;
    if (i < n4) {
        float4 v = ((const float4*)x)[i];
        float vs[4] = {v.x, v.y, v.z, v.w};
        __nv_bfloat16 h[4], l[4];
#pragma unroll
        for (int j = 0; j < 4; j++) {
            h[j] = __float2bfloat16(vs[j]);
            l[j] = __float2bfloat16(vs[j] - __bfloat162float(h[j]));
        }
        ((uint2*)hi)[i] = *(uint2*)h;
        ((uint2*)lo)[i] = *(uint2*)l;
    }
}

// ---------------- fused weight splits (qkv|pre|out|gate) ---------------------
__global__ void __launch_bounds__(256) wsplit_kernel(
    const float* __restrict__ wq, const float* __restrict__ wp,
    const float* __restrict__ wo, const float* __restrict__ wg,
    __nv_bfloat16* __restrict__ hi, __nv_bfloat16* __restrict__ lo)
{
    const int id = blockIdx.x;
    const float* src;
    size_t dbase;
    int local;
    if (id < 108)      { src = wq; local = id;       dbase = 0; }
    else if (id < 144) { src = wp; local = id - 108; dbase = (size_t)3 * CC * CC; }
    else if (id < 180) { src = wo; local = id - 144; dbase = (size_t)4 * CC * CC; }
    else               { src = wg; local = id - 180; dbase = (size_t)5 * CC * CC; }
    const int i = local * 256 + threadIdx.x;
    float4 v = ((const float4*)src)[i];
    float vs[4] = {v.x, v.y, v.z, v.w};
    __nv_bfloat16 h[4], l[4];
#pragma unroll
    for (int j = 0; j < 4; j++) {
        h[j] = __float2bfloat16(vs[j]);
        l[j] = __float2bfloat16(vs[j] - __bfloat162float(h[j]));
    }
    ((uint2*)(hi + dbase))[i] = *(uint2*)h;
    ((uint2*)(lo + dbase))[i] = *(uint2*)l;
}

// ---------------- split-bf16 GEMM, cp.async 3-deep pipeline ------------------
// tile 192m x 64n x 16k; 8 warps (4m x 2n); 4 smem slots.
#define GA_SLOT 18432     // 2 halves x 192 x 24 x 2B
#define GB_BASE 73728     // 4 * GA_SLOT
#define GB_SLOT 4608      // 2 halves x 16 x 72 x 2B
#define GSMEM   92160

__global__ void __launch_bounds__(256, 2) gemm_bf16_kernel(
    const __nv_bfloat16* __restrict__ Whi, const __nv_bfloat16* __restrict__ Wlo,
    const __nv_bfloat16* __restrict__ Xhi, const __nv_bfloat16* __restrict__ Xlo,
    float* __restrict__ Yf, const float* __restrict__ G,
    __nv_bfloat16* __restrict__ Yhi, __nv_bfloat16* __restrict__ Ylo,
    int M, int epi)
{
    extern __shared__ __align__(16) char dsm[];
    const uint32_t sb = smem_u32(dsm);

    const int b  = blockIdx.z;
    const int m0 = blockIdx.y * 192;
    const int n0 = blockIdx.x * 64;
    const size_t xoff = (size_t)b * CC * HWP;

    const int tid  = threadIdx.x;
    const int lane = tid & 31;
    const int warp = tid >> 5;
    const int wm   = (warp >> 1) * 48;
    const int wn   = (warp & 1) * 32;
    const int gq   = lane >> 2;
    const int tg   = lane & 3;

    // per-thread A chunk descriptors (3 x 16B per slot)
    uint32_t aoff[3];
    size_t   agoff[3];
    const __nv_bfloat16* aptr[3];
#pragma unroll
    for (int j = 0; j < 3; j++) {
        const int u = tid + 256 * j;
        const int h = (u >= 384);
        const int v = u - h * 384;
        const int r = v >> 1, c = (v & 1) * 8;
        aoff[j]  = (uint32_t)(h * 9216 + r * 48 + c * 2);
        aptr[j]  = h ? Wlo : Whi;
        agoff[j] = (size_t)(m0 + r) * CC + c;
    }
    // B descriptor (1 x 16B per slot)
    const int bh = tid >> 7, bv = tid & 127;
    const int bk = bv >> 3, bnc = (bv & 7) * 8;
    const uint32_t boff = (uint32_t)(bh * 2304 + bk * 144 + bnc * 2);
    const __nv_bfloat16* bptr = bh ? Xlo : Xhi;
    const size_t bgoff = xoff + (size_t)bk * HWP + n0 + bnc;

    float acc[3][4][4];
#pragma unroll
    for (int mt = 0; mt < 3; mt++)
#pragma unroll
        for (int nt = 0; nt < 4; nt++)
#pragma unroll
            for (int e = 0; e < 4; e++) acc[mt][nt][e] = 0.f;

    // prologue: stages 0..2
#pragma unroll
    for (int s = 0; s < 3; s++) {
        const uint32_t as = sb + s * GA_SLOT;
        const int k0 = s * 16;
#pragma unroll
        for (int j = 0; j < 3; j++) CP_CA(as + aoff[j], aptr[j] + agoff[j] + k0);
        CP_CG(sb + GB_BASE + s * GB_SLOT + boff, bptr + bgoff + (size_t)k0 * HWP);
        CP_COMMIT();
    }

    const int NK = CC / 16;
    for (int i = 0; i < NK; i++) {
        CP_WAIT2();
        __syncthreads();
        if (i + 3 < NK) {
            const int s = (i + 3) & 3;
            const int k0 = (i + 3) * 16;
            const uint32_t as = sb + s * GA_SLOT;
#pragma unroll
            for (int j = 0; j < 3; j++) CP_CA(as + aoff[j], aptr[j] + agoff[j] + k0);
            CP_CG(sb + GB_BASE + s * GB_SLOT + boff, bptr + bgoff + (size_t)k0 * HWP);
        }
        CP_COMMIT();

        const uint32_t As = sb + (uint32_t)(i & 3) * GA_SLOT;
        const uint32_t Bs = sb + GB_BASE + (uint32_t)(i & 3) * GB_SLOT;

        uint32_t bf[2][4][2];
        {
            const uint32_t brow = (uint32_t)(lane & 15) * 144 + (uint32_t)wn * 2;
#pragma unroll
            for (int nt = 0; nt < 4; nt++) {
                ldsm_x2_t(bf[0][nt][0], bf[0][nt][1], Bs + brow + nt * 16);
                ldsm_x2_t(bf[1][nt][0], bf[1][nt][1], Bs + 2304 + brow + nt * 16);
            }
        }
#pragma unroll
        for (int mt = 0; mt < 3; mt++) {
            uint32_t afh[4], afl[4];
            const uint32_t arow = (uint32_t)(wm + mt * 16 + (lane & 15)) * 48
                                + (uint32_t)((lane >> 4) * 16);
            ldsm_x4(afh, As + arow);
            ldsm_x4(afl, As + 9216 + arow);
#pragma unroll
            for (int nt = 0; nt < 4; nt++) {
                mma16816(acc[mt][nt], afh, bf[0][nt][0], bf[0][nt][1]);
                mma16816(acc[mt][nt], afh, bf[1][nt][0], bf[1][nt][1]);
                mma16816(acc[mt][nt], afl, bf[0][nt][0], bf[0][nt][1]);
            }
        }
    }

    // epilogue
    const size_t yoff = (size_t)b * M * HWP;
    const size_t goff = (size_t)b * CC * HWP;
#pragma unroll
    for (int mt = 0; mt < 3; mt++) {
        const int r0 = m0 + wm + mt * 16 + gq;
        const int r1 = r0 + 8;
#pragma unroll
        for (int nt = 0; nt < 4; nt++) {
            const int c = n0 + wn + nt * 8 + 2 * tg;
            float v00 = acc[mt][nt][0], v01 = acc[mt][nt][1];
            float v10 = acc[mt][nt][2], v11 = acc[mt][nt][3];
            if (epi == 1) {
                v00 = v00 / (1.f + __expf(-v00));
                v01 = v01 / (1.f + __expf(-v01));
                v10 = v10 / (1.f + __expf(-v10));
                v11 = v11 / (1.f + __expf(-v11));
            }
            if (epi == 2) {
                float2 g0 = *(const float2*)(G + goff + (size_t)r0 * HWP + c);
                float2 g1 = *(const float2*)(G + goff + (size_t)r1 * HWP + c);
                v00 *= g0.x; v01 *= g0.y; v10 *= g1.x; v11 *= g1.y;
                __nv_bfloat16 h00 = __float2bfloat16(v00);
                __nv_bfloat16 h01 = __float2bfloat16(v01);
                __nv_bfloat16 h10 = __float2bfloat16(v10);
                __nv_bfloat16 h11 = __float2bfloat16(v11);
                *(uint32_t*)(Yhi + yoff + (size_t)r0 * HWP + c) = pack_bf2(h00, h01);
                *(uint32_t*)(Yhi + yoff + (size_t)r1 * HWP + c) = pack_bf2(h10, h11);
                *(uint32_t*)(Ylo + yoff + (size_t)r0 * HWP + c) = pack_bf2(
                    __float2bfloat16(v00 - __bfloat162float(h00)),
                    __float2bfloat16(v01 - __bfloat162float(h01)));
                *(uint32_t*)(Ylo + yoff + (size_t)r1 * HWP + c) = pack_bf2(
                    __float2bfloat16(v10 - __bfloat162float(h10)),
                    __float2bfloat16(v11 - __bfloat162float(h11)));
            } else {
                *(float2*)(Yf + yoff + (size_t)r0 * HWP + c) = make_float2(v00, v01);
                *(float2*)(Yf + yoff + (size_t)r1 * HWP + c) = make_float2(v10, v11);
            }
        }
    }
}

// ---------------- depthwise 3x3, 8 px/thread -> split bf16 -------------------
__global__ void __launch_bounds__(256) dw_kernel(
    const float* __restrict__ t, const float* __restrict__ wd,
    __nv_bfloat16* __restrict__ oh, __nv_bfloat16* __restrict__ ol)
{
    const int cb = blockIdx.y;
    const int c  = cb % (3 * CC);
    const int p  = (blockIdx.x * 256 + threadIdx.x) * 8;
    const int y  = p >> 8;
    const int x  = p & 255;
    const float* base = t + (size_t)cb * HWP;

    float w[9];
#pragma unroll
    for (int i = 0; i < 9; i++) w[i] = wd[c * 9 + i];

    float a[8] = {0.f, 0.f, 0.f, 0.f, 0.f, 0.f, 0.f, 0.f};
#pragma unroll
    for (int dy = -1; dy <= 1; dy++) {
        const int yy = y + dy;
        if (yy < 0 || yy >= HH) continue;
        const float* r = base + yy * WW + x;
        const float4 f0 = *(const float4*)r;
        const float4 f1 = *(const float4*)(r + 4);
        float v[10];
        v[0] = (x > 0) ? r[-1] : 0.f;
        v[1] = f0.x; v[2] = f0.y; v[3] = f0.z; v[4] = f0.w;
        v[5] = f1.x; v[6] = f1.y; v[7] = f1.z; v[8] = f1.w;
        v[9] = (x < 248) ? r[8] : 0.f;
        const float w0 = w[(dy + 1) * 3 + 0];
        const float w1 = w[(dy + 1) * 3 + 1];
        const float w2 = w[(dy + 1) * 3 + 2];
#pragma unroll
        for (int i = 0; i < 8; i++)
            a[i] = fmaf(w0, v[i], fmaf(w1, v[i + 1], fmaf(w2, v[i + 2], a[i])));
    }
    __nv_bfloat16 h[8], l[8];
#pragma unroll
    for (int i = 0; i < 8; i++) {
        h[i] = __float2bfloat16(a[i]);
        l[i] = __float2bfloat16(a[i] - __bfloat162float(h[i]));
    }
    *(uint4*)(oh + (size_t)cb * HWP + p) = *(uint4*)h;
    *(uint4*)(ol + (size_t)cb * HWP + p) = *(uint4*)l;
}

// ---------------- attention via mma.sync v2 (R7, proven) ---------------------
__global__ void __launch_bounds__(256, 2) attn_mma_kernel(
    const __nv_bfloat16* __restrict__ qvh, const __nv_bfloat16* __restrict__ qvl,
    const float* __restrict__ rpb,
    __nv_bfloat16* __restrict__ ohi, __nv_bfloat16* __restrict__ olo)
{
    __shared__ float bsh[512];
    __shared__ __align__(16) __nv_bfloat16 KV[4][32][72];

    const int row = blockIdx.x;
    const int head = blockIdx.y % 6, qh = blockIdx.y / 6;
    const int b = blockIdx.z;
    const int tid = threadIdx.x, lane = tid & 31, warp = tid >> 5;
    const int gq = lane >> 2, tg = lane & 3;
    const size_t base = (((size_t)b * (3 * CC) + head * 32) * HH + row) * WW;
    const size_t koff = (size_t)CC * HWP;
    const float scale2 = 0.17677669529663687f * LOG2E;

    for (int i = tid; i < 511; i += 256) bsh[i] = rpb[i * 6 + head] * LOG2E;

    uint32_t qf[2][2][4];
    {
        __nv_bfloat16* Qst = &KV[0][0][0];
        const int d = tid >> 3, q16 = (tid & 7) * 16;
        const int lrow = ((lane >> 4) & 1) * 8 + (lane & 7);
        const int lcol = warp * 16 + ((lane >> 3) & 1) * 8;
#pragma unroll
        for (int h = 0; h < 2; h++) {
            const __nv_bfloat16* src = h ? qvl : qvh;
            const size_t go = base + (size_t)d * HWP + qh * 128 + q16;
            uint4 v0 = *(const uint4*)(src + go);
            uint4 v1 = *(const uint4*)(src + go + 8);
            __syncthreads();
            *(uint4*)&Qst[d * 136 + q16] = v0;
            *(uint4*)&Qst[d * 136 + q16 + 8] = v1;
            __syncthreads();
#pragma unroll
            for (int ks = 0; ks < 2; ks++)
                ldsm_x4_t(qf[h][ks], smem_u32(&Qst[(ks * 16 + lrow) * 136 + lcol]));
        }
    }

    float m2[2] = {-1e30f, -1e30f}, l2[2] = {0.f, 0.f};
    float o[4][4];
#pragma unroll
    for (int nt = 0; nt < 4; nt++)
#pragma unroll
        for (int e = 0; e < 4; e++) o[nt][e] = 0.f;

    const int cd = tid >> 3, cj = (tid & 7) * 8;
    for (int jt = 0; jt < WW; jt += 64) {
        const size_t kb = base + koff + (size_t)cd * HWP + jt + cj;
        uint4 r0 = *(const uint4*)(qvh + kb);
        uint4 r1 = *(const uint4*)(qvl + kb);
        uint4 r2 = *(const uint4*)(qvh + kb + koff);
        uint4 r3 = *(const uint4*)(qvl + kb + koff);
        __syncthreads();
        *(uint4*)&KV[0][cd][cj] = r0;
        *(uint4*)&KV[1][cd][cj] = r1;
        *(uint4*)&KV[2][cd][cj] = r2;
        *(uint4*)&KV[3][cd][cj] = r3;
        __syncthreads();

        float s[8][4];
#pragma unroll
        for (int nt = 0; nt < 8; nt++)
#pragma unroll
            for (int e = 0; e < 4; e++) s[nt][e] = 0.f;
        const int krow = lane & 15;
#pragma unroll
        for (int ks = 0; ks < 2; ks++) {
            const uint32_t kb0 = smem_u32(&KV[0][ks * 16 + krow][0]);
            const uint32_t kb1 = smem_u32(&KV[1][ks * 16 + krow][0]);
#pragma unroll
            for (int nt = 0; nt < 8; nt++) {
                uint32_t h0, h1, l0, l1;
                ldsm_x2_t(h0, h1, kb0 + nt * 16);
                ldsm_x2_t(l0, l1, kb1 + nt * 16);
                mma16816(s[nt], qf[0][ks], h0, h1);
                mma16816(s[nt], qf[0][ks], l0, l1);
                mma16816(s[nt], qf[1][ks], h0, h1);
            }
        }

        float mx[2] = {m2[0], m2[1]};
        const int i0 = qh * 128 + warp * 16 + gq;
#pragma unroll
        for (int nt = 0; nt < 8; nt++) {
            const int jb = jt + nt * 8 + 2 * tg;
#pragma unroll
            for (int e = 0; e < 4; e++) {
                const int i = i0 + (e >> 1) * 8;
                const int j = jb + (e & 1);
                const float t = fmaf(s[nt][e], scale2, bsh[i - j + 255]);
                s[nt][e] = t;
                mx[e >> 1] = fmaxf(mx[e >> 1], t);
            }
        }
#pragma unroll
        for (int sl = 0; sl < 2; sl++) {
            float v = mx[sl];
            v = fmaxf(v, __shfl_xor_sync(0xFFFFFFFFu, v, 1));
            v = fmaxf(v, __shfl_xor_sync(0xFFFFFFFFu, v, 2));
            mx[sl] = v;
        }
        float cf[2];
#pragma unroll
        for (int sl = 0; sl < 2; sl++) {
            cf[sl] = exp2f(m2[sl] - mx[sl]);
            m2[sl] = mx[sl];
            l2[sl] *= cf[sl];
        }
#pragma unroll
        for (int nt = 0; nt < 4; nt++)
#pragma unroll
            for (int e = 0; e < 4; e++) o[nt][e] *= cf[e >> 1];

        float rs[2] = {0.f, 0.f};
#pragma unroll
        for (int kp = 0; kp < 4; kp++) {
            uint32_t pfh[4], pfl[4];
#pragma unroll
            for (int h2 = 0; h2 < 2; h2++) {
                const int nt = 2 * kp + h2;
                float p0 = exp2f(s[nt][0] - m2[0]);
                float p1 = exp2f(s[nt][1] - m2[0]);
                float p2 = exp2f(s[nt][2] - m2[1]);
                float p3 = exp2f(s[nt][3] - m2[1]);
                rs[0] += p0 + p1;
                rs[1] += p2 + p3;
                __nv_bfloat16 h0 = __float2bfloat16(p0);
                __nv_bfloat16 h1 = __float2bfloat16(p1);
                __nv_bfloat16 h2b = __float2bfloat16(p2);
                __nv_bfloat16 h3 = __float2bfloat16(p3);
                pfh[h2 * 2 + 0] = pack_bf2(h0, h1);
                pfh[h2 * 2 + 1] = pack_bf2(h2b, h3);
                pfl[h2 * 2 + 0] = pack_bf2(
                    __float2bfloat16(p0 - __bfloat162float(h0)),
                    __float2bfloat16(p1 - __bfloat162float(h1)));
                pfl[h2 * 2 + 1] = pack_bf2(
                    __float2bfloat16(p2 - __bfloat162float(h2b)),
                    __float2bfloat16(p3 - __bfloat162float(h3)));
            }
            const int vr = lane & 7, vk = kp * 16 + ((lane >> 3) & 1) * 8;
#pragma unroll
            for (int ntv = 0; ntv < 4; ntv++) {
                uint32_t vh0, vh1, vl0, vl1;
                ldsm_x2(vh0, vh1, smem_u32(&KV[2][ntv * 8 + vr][vk]));
                ldsm_x2(vl0, vl1, smem_u32(&KV[3][ntv * 8 + vr][vk]));
                mma16816(o[ntv], pfh, vh0, vh1);
                mma16816(o[ntv], pfh, vl0, vl1);
                mma16816(o[ntv], pfl, vh0, vh1);
            }
        }
#pragma unroll
        for (int sl = 0; sl < 2; sl++) {
            float r = rs[sl];
            r += __shfl_xor_sync(0xFFFFFFFFu, r, 1);
            r += __shfl_xor_sync(0xFFFFFFFFu, r, 2);
            l2[sl] += r;
        }
    }

    __syncthreads();
    float* stage = (float*)&KV[0][0][0];
    const float inv0 = 1.f / l2[0], inv1 = 1.f / l2[1];
#pragma unroll
    for (int nt = 0; nt < 4; nt++) {
        const int c = nt * 8 + 2 * tg;
#pragma unroll
        for (int e = 0; e < 4; e++) {
            const int rr = warp * 16 + gq + (e >> 1) * 8;
            stage[rr * 33 + c + (e & 1)] = o[nt][e] * ((e >> 1) ? inv1 : inv0);
        }
    }
    __syncthreads();
    const size_t obase = (((size_t)b * CC + head * 32) * HH + row) * WW + qh * 128;
    const int q = tid & 127, db = (tid >> 7) * 16;
#pragma unroll
    for (int dd = 0; dd < 16; dd++) {
        const int d = db + dd;
        const float v = stage[q * 33 + d];
        __nv_bfloat16 h = __float2bfloat16(v);
        ohi[obase + (size_t)d * HWP + q] = h;
        olo[obase + (size_t)d * HWP + q] = __float2bfloat16(v - __bfloat162float(h));
    }
}

// ---------------- launch ------------------------------------------------------
extern "C" void kernel_launch(void* const* d_in, const int* in_sizes, int n_in,
                              void* d_out, int out_size)
{
    const float* x       = (const float*)d_in[0];
    const float* rpb     = (const float*)d_in[1];
    const float* w_qkv   = (const float*)d_in[2];
    const float* w_depth = (const float*)d_in[3];
    const float* w_pre   = (const float*)d_in[4];
    const float* w_out   = (const float*)d_in[5];
    const float* w_gate  = (const float*)d_in[6];
    float* out = (float*)d_out;
    (void)in_sizes; (void)n_in; (void)out_size;

    float *gate, *t, *qkvf;
    __nv_bfloat16 *xhi, *xlo, *ahi, *alo, *yhi, *ylo, *whi, *wlo;
    cudaGetSymbolAddress((void**)&gate, g_gate);
    cudaGetSymbolAddress((void**)&t,    g_t);
    cudaGetSymbolAddress((void**)&qkvf, g_qkv);
    cudaGetSymbolAddress((void**)&xhi,  g_xhi);
    cudaGetSymbolAddress((void**)&xlo,  g_xlo);
    cudaGetSymbolAddress((void**)&ahi,  g_ahi);
    cudaGetSymbolAddress((void**)&alo,  g_alo);
    cudaGetSymbolAddress((void**)&yhi,  g_yhi);
    cudaGetSymbolAddress((void**)&ylo,  g_ylo);
    cudaGetSymbolAddress((void**)&whi,  g_whi);
    cudaGetSymbolAddress((void**)&wlo,  g_wlo);
    __nv_bfloat16* qvh = (__nv_bfloat16*)qkvf;
    __nv_bfloat16* qvl = qvh + (size_t)NB * 3 * CC * HWP;

    cudaFuncSetAttribute(gemm_bf16_kernel,
                         cudaFuncAttributeMaxDynamicSharedMemorySize, GSMEM);

    const int WS = CC * CC;
    const int nx = NB * CC * HWP;
    split4_kernel<<<(nx / 4 + 255) / 256, 256>>>(x, xhi, xlo, nx / 4);
    wsplit_kernel<<<216, 256>>>(w_qkv, w_pre, w_out, w_gate, whi, wlo);

    const dim3 gSmall(HWP / 64, 1, NB);
    const dim3 gQkv(HWP / 64, 3, NB);

    // t = W_qkv @ x
    gemm_bf16_kernel<<<gQkv, 256, GSMEM>>>(whi, wlo, xhi, xlo,
                                           t, nullptr, nullptr, nullptr, 3 * CC, 0);
    // qkv = depthwise3x3(t) -> split bf16
    dw_kernel<<<dim3(HWP / 2048, NB * 3 * CC), 256>>>(t, w_depth, qvh, qvl);
    // attention -> split bf16
    attn_mma_kernel<<<dim3(HH, 12, NB), 256>>>(qvh, qvl, rpb, ahi, alo);
    // gate = silu(W_gate @ x)
    gemm_bf16_kernel<<<gSmall, 256, GSMEM>>>(whi + 5 * WS, wlo + 5 * WS, xhi, xlo,
                                             gate, nullptr, nullptr, nullptr, CC, 1);
    // y = (W_pre @ attn) * gate -> split bf16
    gemm_bf16_kernel<<<gSmall, 256, GSMEM>>>(whi + 3 * WS, wlo + 3 * WS, ahi, alo,
                                             nullptr, gate, yhi, ylo, CC, 2);
    // out = W_out @ y
    gemm_bf16_kernel<<<gSmall, 256, GSMEM>>>(whi + 4 * WS, wlo + 4 * WS, yhi, ylo,
                                             out, nullptr, nullptr, nullptr, CC, 0);
}

// round 9
// speedup vs baseline: 2.7099x; 1.4015x over previous
#include <cuda_runtime.h>
#include <cuda_bf16.h>
#include <cuda_fp16.h>
#include <math.h>
#include <stdint.h>

#define HH 128
#define WW 256
#define CC 192
#define HWP (128*256)
#define NB 2
#define LOG2E 1.4426950408889634f

// ---------------- scratch (device globals) ----------------------------------
__device__ float g_gate[NB * CC * HWP];
__device__ float g_t[NB * 3 * CC * HWP];
__device__ __half g_qv[NB * 3 * CC * HWP];     // q,k,v fp16 (dw output)
__device__ __half g_xh[NB * CC * HWP];         // x fp16
__device__ __half g_ah[NB * CC * HWP];         // attn out fp16
__device__ __half g_yh[NB * CC * HWP];         // pre*gate fp16
__device__ __half g_whi[6 * CC * CC];
__device__ __half g_wlo[6 * CC * CC];

// ---------------- helpers -----------------------------------------------------
__device__ __forceinline__ uint32_t smem_u32(const void* p) {
    uint32_t a;
    asm("{ .reg .u64 t; cvta.to.shared.u64 t, %1; cvt.u32.u64 %0, t; }" : "=r"(a) : "l"(p));
    return a;
}
__device__ __forceinline__ void mma16816h(float* c, const uint32_t* a,
                                          uint32_t b0, uint32_t b1)
{
    asm volatile(
        "mma.sync.aligned.m16n8k16.row.col.f32.f16.f16.f32 "
        "{%0,%1,%2,%3}, {%4,%5,%6,%7}, {%8,%9}, {%0,%1,%2,%3};\n"
        : "+f"(c[0]), "+f"(c[1]), "+f"(c[2]), "+f"(c[3])
        : "r"(a[0]), "r"(a[1]), "r"(a[2]), "r"(a[3]), "r"(b0), "r"(b1));
}
__device__ __forceinline__ void ldsm_x4(uint32_t* d, uint32_t a) {
    asm volatile("ldmatrix.sync.aligned.m8n8.x4.shared.b16 {%0,%1,%2,%3}, [%4];\n"
                 : "=r"(d[0]), "=r"(d[1]), "=r"(d[2]), "=r"(d[3]) : "r"(a));
}
__device__ __forceinline__ void ldsm_x4_t(uint32_t* d, uint32_t a) {
    asm volatile("ldmatrix.sync.aligned.m8n8.x4.trans.shared.b16 {%0,%1,%2,%3}, [%4];\n"
                 : "=r"(d[0]), "=r"(d[1]), "=r"(d[2]), "=r"(d[3]) : "r"(a));
}
__device__ __forceinline__ void ldsm_x2(uint32_t& d0, uint32_t& d1, uint32_t a) {
    asm volatile("ldmatrix.sync.aligned.m8n8.x2.shared.b16 {%0,%1}, [%2];\n"
                 : "=r"(d0), "=r"(d1) : "r"(a));
}
__device__ __forceinline__ void ldsm_x2_t(uint32_t& d0, uint32_t& d1, uint32_t a) {
    asm volatile("ldmatrix.sync.aligned.m8n8.x2.trans.shared.b16 {%0,%1}, [%2];\n"
                 : "=r"(d0), "=r"(d1) : "r"(a));
}
__device__ __forceinline__ uint32_t pack_h2(__half a, __half b) {
    __half2 t = __halves2half2(a, b);
    return *(uint32_t*)&t;
}
#define CP_CA(d, s) asm volatile("cp.async.ca.shared.global [%0], [%1], 16;\n" :: "r"(d), "l"(s))
#define CP_CG(d, s) asm volatile("cp.async.cg.shared.global [%0], [%1], 16;\n" :: "r"(d), "l"(s))
#define CP_COMMIT() asm volatile("cp.async.commit_group;\n" ::: "memory")
#define CP_WAIT2()  asm volatile("cp.async.wait_group 2;\n" ::: "memory")

// ---------------- fp32 -> fp16, 4/thread -------------------------------------
__global__ void __launch_bounds__(256) cvt4_kernel(
    const float* __restrict__ x, __half* __restrict__ h, int n4)
{
    int i = blockIdx.x * 256 + threadIdx.x;
    if (i < n4) {
        float4 v = ((const float4*)x)[i];
        __half hh[4] = {__float2half(v.x), __float2half(v.y),
                        __float2half(v.z), __float2half(v.w)};
        ((uint2*)h)[i] = *(uint2*)hh;
    }
}

// ---------------- fused weight splits (fp16 hi/lo) ---------------------------
__global__ void __launch_bounds__(256) wsplit_kernel(
    const float* __restrict__ wq, const float* __restrict__ wp,
    const float* __restrict__ wo, const float* __restrict__ wg,
    __half* __restrict__ hi, __half* __restrict__ lo)
{
    const int id = blockIdx.x;
    const float* src;
    size_t dbase;
    int local;
    if (id < 108)      { src = wq; local = id;       dbase = 0; }
    else if (id < 144) { src = wp; local = id - 108; dbase = (size_t)3 * CC * CC; }
    else if (id < 180) { src = wo; local = id - 144; dbase = (size_t)4 * CC * CC; }
    else               { src = wg; local = id - 180; dbase = (size_t)5 * CC * CC; }
    const int i = local * 256 + threadIdx.x;
    float4 v = ((const float4*)src)[i];
    float vs[4] = {v.x, v.y, v.z, v.w};
    __half h[4], l[4];
#pragma unroll
    for (int j = 0; j < 4; j++) {
        h[j] = __float2half(vs[j]);
        l[j] = __float2half(vs[j] - __half2float(h[j]));
    }
    ((uint2*)(hi + dbase))[i] = *(uint2*)h;
    ((uint2*)(lo + dbase))[i] = *(uint2*)l;
}

// ---------------- fp16 W-split GEMM, cp.async 3-deep pipeline ----------------
// Y[b,m,p] = sum_c W[m,c]*X[b,c,p]; W = Whi+Wlo (fp16), X single fp16.
// tile 192m x 64n x 16k; 8 warps (4m x 2n); 24 mma/iter/warp.
#define GA_SLOT 18432     // 2 halves x 192 rows x 48B
#define GB_BASE 73728
#define GB_SLOT 2304      // 16 x 72 halfs x 2B
#define GSMEM   82944

__global__ void __launch_bounds__(256, 2) gemm_fp16_kernel(
    const __half* __restrict__ Whi, const __half* __restrict__ Wlo,
    const __half* __restrict__ Xh,
    float* __restrict__ Yf, const float* __restrict__ G,
    __half* __restrict__ Yh, int M, int epi)
{
    extern __shared__ __align__(16) char dsm[];
    const uint32_t sb = smem_u32(dsm);

    const int b  = blockIdx.z;
    const int m0 = blockIdx.y * 192;
    const int n0 = blockIdx.x * 64;
    const size_t xoff = (size_t)b * CC * HWP;

    const int tid  = threadIdx.x;
    const int lane = tid & 31;
    const int warp = tid >> 5;
    const int wm   = (warp >> 1) * 48;
    const int wn   = (warp & 1) * 32;
    const int gq   = lane >> 2;
    const int tg   = lane & 3;

    uint32_t aoff[3];
    size_t   agoff[3];
    const __half* aptr[3];
#pragma unroll
    for (int j = 0; j < 3; j++) {
        const int u = tid + 256 * j;
        const int h = (u >= 384);
        const int v = u - h * 384;
        const int r = v >> 1, c = (v & 1) * 8;
        aoff[j]  = (uint32_t)(h * 9216 + r * 48 + c * 2);
        aptr[j]  = h ? Wlo : Whi;
        agoff[j] = (size_t)(m0 + r) * CC + c;
    }
    const int doB = (tid < 128);
    const int bk = (tid & 127) >> 3, bnc = (tid & 7) * 8;
    const uint32_t boff = (uint32_t)(bk * 144 + bnc * 2);
    const size_t bgoff = xoff + (size_t)bk * HWP + n0 + bnc;

    float acc[3][4][4];
#pragma unroll
    for (int mt = 0; mt < 3; mt++)
#pragma unroll
        for (int nt = 0; nt < 4; nt++)
#pragma unroll
            for (int e = 0; e < 4; e++) acc[mt][nt][e] = 0.f;

#pragma unroll
    for (int s = 0; s < 3; s++) {
        const uint32_t as = sb + s * GA_SLOT;
        const int k0 = s * 16;
#pragma unroll
        for (int j = 0; j < 3; j++) CP_CA(as + aoff[j], aptr[j] + agoff[j] + k0);
        if (doB) CP_CG(sb + GB_BASE + s * GB_SLOT + boff, Xh + bgoff + (size_t)k0 * HWP);
        CP_COMMIT();
    }

    const int NK = CC / 16;
    for (int i = 0; i < NK; i++) {
        CP_WAIT2();
        __syncthreads();
        if (i + 3 < NK) {
            const int s = (i + 3) & 3;
            const int k0 = (i + 3) * 16;
            const uint32_t as = sb + s * GA_SLOT;
#pragma unroll
            for (int j = 0; j < 3; j++) CP_CA(as + aoff[j], aptr[j] + agoff[j] + k0);
            if (doB) CP_CG(sb + GB_BASE + s * GB_SLOT + boff, Xh + bgoff + (size_t)k0 * HWP);
        }
        CP_COMMIT();

        const uint32_t As = sb + (uint32_t)(i & 3) * GA_SLOT;
        const uint32_t Bs = sb + GB_BASE + (uint32_t)(i & 3) * GB_SLOT;

        uint32_t bf[4][2];
        {
            const uint32_t brow = (uint32_t)(lane & 15) * 144 + (uint32_t)wn * 2;
#pragma unroll
            for (int nt = 0; nt < 4; nt++)
                ldsm_x2_t(bf[nt][0], bf[nt][1], Bs + brow + nt * 16);
        }
#pragma unroll
        for (int mt = 0; mt < 3; mt++) {
            uint32_t afh[4], afl[4];
            const uint32_t arow = (uint32_t)(wm + mt * 16 + (lane & 15)) * 48
                                + (uint32_t)((lane >> 4) * 16);
            ldsm_x4(afh, As + arow);
            ldsm_x4(afl, As + 9216 + arow);
#pragma unroll
            for (int nt = 0; nt < 4; nt++) {
                mma16816h(acc[mt][nt], afh, bf[nt][0], bf[nt][1]);
                mma16816h(acc[mt][nt], afl, bf[nt][0], bf[nt][1]);
            }
        }
    }

    const size_t yoff = (size_t)b * M * HWP;
    const size_t goff = (size_t)b * CC * HWP;
#pragma unroll
    for (int mt = 0; mt < 3; mt++) {
        const int r0 = m0 + wm + mt * 16 + gq;
        const int r1 = r0 + 8;
#pragma unroll
        for (int nt = 0; nt < 4; nt++) {
            const int c = n0 + wn + nt * 8 + 2 * tg;
            float v00 = acc[mt][nt][0], v01 = acc[mt][nt][1];
            float v10 = acc[mt][nt][2], v11 = acc[mt][nt][3];
            if (epi == 1) {
                v00 = v00 / (1.f + __expf(-v00));
                v01 = v01 / (1.f + __expf(-v01));
                v10 = v10 / (1.f + __expf(-v10));
                v11 = v11 / (1.f + __expf(-v11));
            }
            if (epi == 2) {
                float2 g0 = *(const float2*)(G + goff + (size_t)r0 * HWP + c);
                float2 g1 = *(const float2*)(G + goff + (size_t)r1 * HWP + c);
                v00 *= g0.x; v01 *= g0.y; v10 *= g1.x; v11 *= g1.y;
                *(uint32_t*)(Yh + yoff + (size_t)r0 * HWP + c) =
                    pack_h2(__float2half(v00), __float2half(v01));
                *(uint32_t*)(Yh + yoff + (size_t)r1 * HWP + c) =
                    pack_h2(__float2half(v10), __float2half(v11));
            } else {
                *(float2*)(Yf + yoff + (size_t)r0 * HWP + c) = make_float2(v00, v01);
                *(float2*)(Yf + yoff + (size_t)r1 * HWP + c) = make_float2(v10, v11);
            }
        }
    }
}

// ---------------- depthwise 3x3, 8 px/thread -> fp16 -------------------------
__global__ void __launch_bounds__(256) dw_kernel(
    const float* __restrict__ t, const float* __restrict__ wd,
    __half* __restrict__ oh)
{
    const int cb = blockIdx.y;
    const int c  = cb % (3 * CC);
    const int p  = (blockIdx.x * 256 + threadIdx.x) * 8;
    const int y  = p >> 8;
    const int x  = p & 255;
    const float* base = t + (size_t)cb * HWP;

    float w[9];
#pragma unroll
    for (int i = 0; i < 9; i++) w[i] = wd[c * 9 + i];

    float a[8] = {0.f, 0.f, 0.f, 0.f, 0.f, 0.f, 0.f, 0.f};
#pragma unroll
    for (int dy = -1; dy <= 1; dy++) {
        const int yy = y + dy;
        if (yy < 0 || yy >= HH) continue;
        const float* r = base + yy * WW + x;
        const float4 f0 = *(const float4*)r;
        const float4 f1 = *(const float4*)(r + 4);
        float v[10];
        v[0] = (x > 0) ? r[-1] : 0.f;
        v[1] = f0.x; v[2] = f0.y; v[3] = f0.z; v[4] = f0.w;
        v[5] = f1.x; v[6] = f1.y; v[7] = f1.z; v[8] = f1.w;
        v[9] = (x < 248) ? r[8] : 0.f;
        const float w0 = w[(dy + 1) * 3 + 0];
        const float w1 = w[(dy + 1) * 3 + 1];
        const float w2 = w[(dy + 1) * 3 + 2];
#pragma unroll
        for (int i = 0; i < 8; i++)
            a[i] = fmaf(w0, v[i], fmaf(w1, v[i + 1], fmaf(w2, v[i + 2], a[i])));
    }
    __half h[8];
#pragma unroll
    for (int i = 0; i < 8; i++) h[i] = __float2half(a[i]);
    *(uint4*)(oh + (size_t)cb * HWP + p) = *(uint4*)h;
}

// ---------------- attention, fp16 single-product -----------------------------
// block = (row, qhalf*head, b); 8 warps x 16 queries = 128 q/block.
__global__ void __launch_bounds__(256, 2) attn_mma_kernel(
    const __half* __restrict__ qv, const float* __restrict__ rpb,
    __half* __restrict__ oa)
{
    __shared__ float bsh[512];
    __shared__ __align__(16) __half KV[2][32][72];     // K, V  [d][j]
    __shared__ __align__(16) float stage[128 * 33];    // also Q staging

    const int row = blockIdx.x;
    const int head = blockIdx.y % 6, qh = blockIdx.y / 6;
    const int b = blockIdx.z;
    const int tid = threadIdx.x, lane = tid & 31, warp = tid >> 5;
    const int gq = lane >> 2, tg = lane & 3;
    const size_t base = (((size_t)b * (3 * CC) + head * 32) * HH + row) * WW;
    const size_t koff = (size_t)CC * HWP;
    const float scale2 = 0.17677669529663687f * LOG2E;

    for (int i = tid; i < 511; i += 256) bsh[i] = rpb[i * 6 + head] * LOG2E;

    // ---- stage Q through `stage`, build A fragments ----
    uint32_t qf[2][4];
    {
        __half* Qst = (__half*)stage;                 // [32][136]
        const int d = tid >> 3, q16 = (tid & 7) * 16;
        const size_t go = base + (size_t)d * HWP + qh * 128 + q16;
        uint4 v0 = *(const uint4*)(qv + go);
        uint4 v1 = *(const uint4*)(qv + go + 8);
        *(uint4*)&Qst[d * 136 + q16] = v0;
        *(uint4*)&Qst[d * 136 + q16 + 8] = v1;
        __syncthreads();
        const int lrow = ((lane >> 4) & 1) * 8 + (lane & 7);
        const int lcol = warp * 16 + ((lane >> 3) & 1) * 8;
#pragma unroll
        for (int ks = 0; ks < 2; ks++)
            ldsm_x4_t(qf[ks], smem_u32(&Qst[(ks * 16 + lrow) * 136 + lcol]));
        __syncthreads();
    }

    float m2[2] = {-1e30f, -1e30f}, l2[2] = {0.f, 0.f};
    float o[4][4];
#pragma unroll
    for (int nt = 0; nt < 4; nt++)
#pragma unroll
        for (int e = 0; e < 4; e++) o[nt][e] = 0.f;

    const int cd = tid >> 3, cj = (tid & 7) * 8;
    for (int jt = 0; jt < WW; jt += 64) {
        const size_t kb = base + koff + (size_t)cd * HWP + jt + cj;
        uint4 rK = *(const uint4*)(qv + kb);
        uint4 rV = *(const uint4*)(qv + kb + koff);
        __syncthreads();
        *(uint4*)&KV[0][cd][cj] = rK;
        *(uint4*)&KV[1][cd][cj] = rV;
        __syncthreads();

        // S = Q K^T (single product)
        float s[8][4];
#pragma unroll
        for (int nt = 0; nt < 8; nt++)
#pragma unroll
            for (int e = 0; e < 4; e++) s[nt][e] = 0.f;
        const int krow = lane & 15;
#pragma unroll
        for (int ks = 0; ks < 2; ks++) {
            const uint32_t kb0 = smem_u32(&KV[0][ks * 16 + krow][0]);
#pragma unroll
            for (int nt = 0; nt < 8; nt++) {
                uint32_t h0, h1;
                ldsm_x2_t(h0, h1, kb0 + nt * 16);
                mma16816h(s[nt], qf[ks], h0, h1);
            }
        }

        float mx[2] = {m2[0], m2[1]};
        const int i0 = qh * 128 + warp * 16 + gq;
#pragma unroll
        for (int nt = 0; nt < 8; nt++) {
            const int jb = jt + nt * 8 + 2 * tg;
#pragma unroll
            for (int e = 0; e < 4; e++) {
                const int i = i0 + (e >> 1) * 8;
                const int j = jb + (e & 1);
                const float t = fmaf(s[nt][e], scale2, bsh[i - j + 255]);
                s[nt][e] = t;
                mx[e >> 1] = fmaxf(mx[e >> 1], t);
            }
        }
#pragma unroll
        for (int sl = 0; sl < 2; sl++) {
            float v = mx[sl];
            v = fmaxf(v, __shfl_xor_sync(0xFFFFFFFFu, v, 1));
            v = fmaxf(v, __shfl_xor_sync(0xFFFFFFFFu, v, 2));
            mx[sl] = v;
        }
        float cf[2];
#pragma unroll
        for (int sl = 0; sl < 2; sl++) {
            cf[sl] = exp2f(m2[sl] - mx[sl]);
            m2[sl] = mx[sl];
            l2[sl] *= cf[sl];
        }
#pragma unroll
        for (int nt = 0; nt < 4; nt++)
#pragma unroll
            for (int e = 0; e < 4; e++) o[nt][e] *= cf[e >> 1];

        // P = exp2(S - m); PV (single product)
        float rs[2] = {0.f, 0.f};
#pragma unroll
        for (int kp = 0; kp < 4; kp++) {
            uint32_t pf[4];
#pragma unroll
            for (int h2 = 0; h2 < 2; h2++) {
                const int nt = 2 * kp + h2;
                float p0 = exp2f(s[nt][0] - m2[0]);
                float p1 = exp2f(s[nt][1] - m2[0]);
                float p2 = exp2f(s[nt][2] - m2[1]);
                float p3 = exp2f(s[nt][3] - m2[1]);
                rs[0] += p0 + p1;
                rs[1] += p2 + p3;
                pf[h2 * 2 + 0] = pack_h2(__float2half(p0), __float2half(p1));
                pf[h2 * 2 + 1] = pack_h2(__float2half(p2), __float2half(p3));
            }
            const int vr = lane & 7, vk = kp * 16 + ((lane >> 3) & 1) * 8;
#pragma unroll
            for (int ntv = 0; ntv < 4; ntv++) {
                uint32_t v0, v1;
                ldsm_x2(v0, v1, smem_u32(&KV[1][ntv * 8 + vr][vk]));
                mma16816h(o[ntv], pf, v0, v1);
            }
        }
#pragma unroll
        for (int sl = 0; sl < 2; sl++) {
            float r = rs[sl];
            r += __shfl_xor_sync(0xFFFFFFFFu, r, 1);
            r += __shfl_xor_sync(0xFFFFFFFFu, r, 2);
            l2[sl] += r;
        }
    }

    __syncthreads();
    const float inv0 = 1.f / l2[0], inv1 = 1.f / l2[1];
#pragma unroll
    for (int nt = 0; nt < 4; nt++) {
        const int c = nt * 8 + 2 * tg;
#pragma unroll
        for (int e = 0; e < 4; e++) {
            const int rr = warp * 16 + gq + (e >> 1) * 8;
            stage[rr * 33 + c + (e & 1)] = o[nt][e] * ((e >> 1) ? inv1 : inv0);
        }
    }
    __syncthreads();
    const size_t obase = (((size_t)b * CC + head * 32) * HH + row) * WW + qh * 128;
    const int q = tid & 127, db = (tid >> 7) * 16;
#pragma unroll
    for (int dd = 0; dd < 16; dd++) {
        const int d = db + dd;
        oa[obase + (size_t)d * HWP + q] = __float2half(stage[q * 33 + d]);
    }
}

// ---------------- launch ------------------------------------------------------
extern "C" void kernel_launch(void* const* d_in, const int* in_sizes, int n_in,
                              void* d_out, int out_size)
{
    const float* x       = (const float*)d_in[0];
    const float* rpb     = (const float*)d_in[1];
    const float* w_qkv   = (const float*)d_in[2];
    const float* w_depth = (const float*)d_in[3];
    const float* w_pre   = (const float*)d_in[4];
    const float* w_out   = (const float*)d_in[5];
    const float* w_gate  = (const float*)d_in[6];
    float* out = (float*)d_out;
    (void)in_sizes; (void)n_in; (void)out_size;

    float *gate, *t;
    __half *qv, *xh, *ah, *yh, *whi, *wlo;
    cudaGetSymbolAddress((void**)&gate, g_gate);
    cudaGetSymbolAddress((void**)&t,    g_t);
    cudaGetSymbolAddress((void**)&qv,   g_qv);
    cudaGetSymbolAddress((void**)&xh,   g_xh);
    cudaGetSymbolAddress((void**)&ah,   g_ah);
    cudaGetSymbolAddress((void**)&yh,   g_yh);
    cudaGetSymbolAddress((void**)&whi,  g_whi);
    cudaGetSymbolAddress((void**)&wlo,  g_wlo);

    cudaFuncSetAttribute(gemm_fp16_kernel,
                         cudaFuncAttributeMaxDynamicSharedMemorySize, GSMEM);

    const int WS = CC * CC;
    const int nx = NB * CC * HWP;
    cvt4_kernel<<<(nx / 4 + 255) / 256, 256>>>(x, xh, nx / 4);
    wsplit_kernel<<<216, 256>>>(w_qkv, w_pre, w_out, w_gate, whi, wlo);

    const dim3 gSmall(HWP / 64, 1, NB);
    const dim3 gQkv(HWP / 64, 3, NB);

    // t = W_qkv @ x
    gemm_fp16_kernel<<<gQkv, 256, GSMEM>>>(whi, wlo, xh,
                                           t, nullptr, nullptr, 3 * CC, 0);
    // q,k,v = depthwise3x3(t) -> fp16
    dw_kernel<<<dim3(HWP / 2048, NB * 3 * CC), 256>>>(t, w_depth, qv);
    // attention -> fp16
    attn_mma_kernel<<<dim3(HH, 12, NB), 256>>>(qv, rpb, ah);
    // gate = silu(W_gate @ x)
    gemm_fp16_kernel<<<gSmall, 256, GSMEM>>>(whi + 5 * WS, wlo + 5 * WS, xh,
                                             gate, nullptr, nullptr, CC, 1);
    // y = (W_pre @ attn) * gate -> fp16
    gemm_fp16_kernel<<<gSmall, 256, GSMEM>>>(whi + 3 * WS, wlo + 3 * WS, ah,
                                             nullptr, gate, yh, CC, 2);
    // out = W_out @ y
    gemm_fp16_kernel<<<gSmall, 256, GSMEM>>>(whi + 4 * WS, wlo + 4 * WS, yh,
                                             out, nullptr, nullptr, CC, 0);
}

// round 10
// speedup vs baseline: 2.8159x; 1.0391x over previous
#include <cuda_runtime.h>
#include <cuda_bf16.h>
#include <cuda_fp16.h>
#include <math.h>
#include <stdint.h>

#define HH 128
#define WW 256
#define CC 192
#define HWP (128*256)
#define NB 2
#define LOG2E 1.4426950408889634f

// ---------------- scratch (device globals) ----------------------------------
__device__ float g_gate[NB * CC * HWP];
__device__ float g_t[NB * 3 * CC * HWP];
__device__ __half g_qv[NB * 3 * CC * HWP];     // q,k,v fp16 (dw output)
__device__ __half g_xh[NB * CC * HWP];         // x fp16
__device__ __half g_ah[NB * CC * HWP];         // attn out fp16
__device__ __half g_yh[NB * CC * HWP];         // pre*gate fp16
__device__ __half g_whi[6 * CC * CC];          // [qkv|gate|pre|out]
__device__ __half g_wlo[6 * CC * CC];

// ---------------- helpers -----------------------------------------------------
__device__ __forceinline__ uint32_t smem_u32(const void* p) {
    uint32_t a;
    asm("{ .reg .u64 t; cvta.to.shared.u64 t, %1; cvt.u32.u64 %0, t; }" : "=r"(a) : "l"(p));
    return a;
}
__device__ __forceinline__ void mma16816h(float* c, const uint32_t* a,
                                          uint32_t b0, uint32_t b1)
{
    asm volatile(
        "mma.sync.aligned.m16n8k16.row.col.f32.f16.f16.f32 "
        "{%0,%1,%2,%3}, {%4,%5,%6,%7}, {%8,%9}, {%0,%1,%2,%3};\n"
        : "+f"(c[0]), "+f"(c[1]), "+f"(c[2]), "+f"(c[3])
        : "r"(a[0]), "r"(a[1]), "r"(a[2]), "r"(a[3]), "r"(b0), "r"(b1));
}
__device__ __forceinline__ void ldsm_x4(uint32_t* d, uint32_t a) {
    asm volatile("ldmatrix.sync.aligned.m8n8.x4.shared.b16 {%0,%1,%2,%3}, [%4];\n"
                 : "=r"(d[0]), "=r"(d[1]), "=r"(d[2]), "=r"(d[3]) : "r"(a));
}
__device__ __forceinline__ void ldsm_x4_t(uint32_t* d, uint32_t a) {
    asm volatile("ldmatrix.sync.aligned.m8n8.x4.trans.shared.b16 {%0,%1,%2,%3}, [%4];\n"
                 : "=r"(d[0]), "=r"(d[1]), "=r"(d[2]), "=r"(d[3]) : "r"(a));
}
__device__ __forceinline__ void ldsm_x2(uint32_t& d0, uint32_t& d1, uint32_t a) {
    asm volatile("ldmatrix.sync.aligned.m8n8.x2.shared.b16 {%0,%1}, [%2];\n"
                 : "=r"(d0), "=r"(d1) : "r"(a));
}
__device__ __forceinline__ void ldsm_x2_t(uint32_t& d0, uint32_t& d1, uint32_t a) {
    asm volatile("ldmatrix.sync.aligned.m8n8.x2.trans.shared.b16 {%0,%1}, [%2];\n"
                 : "=r"(d0), "=r"(d1) : "r"(a));
}
__device__ __forceinline__ uint32_t pack_h2(__half a, __half b) {
    __half2 t = __halves2half2(a, b);
    return *(uint32_t*)&t;
}
#define CP_CA(d, s) asm volatile("cp.async.ca.shared.global [%0], [%1], 16;\n" :: "r"(d), "l"(s))
#define CP_CG(d, s) asm volatile("cp.async.cg.shared.global [%0], [%1], 16;\n" :: "r"(d), "l"(s))
#define CP_COMMIT() asm volatile("cp.async.commit_group;\n" ::: "memory")
#define CP_WAIT2()  asm volatile("cp.async.wait_group 2;\n" ::: "memory")
#define CP_WAIT1()  asm volatile("cp.async.wait_group 1;\n" ::: "memory")
#define CP_WAIT0()  asm volatile("cp.async.wait_group 0;\n" ::: "memory")

// ---------------- fp32 -> fp16, 4/thread -------------------------------------
__global__ void __launch_bounds__(256) cvt4_kernel(
    const float* __restrict__ x, __half* __restrict__ h, int n4)
{
    int i = blockIdx.x * 256 + threadIdx.x;
    if (i < n4) {
        float4 v = ((const float4*)x)[i];
        __half hh[4] = {__float2half(v.x), __float2half(v.y),
                        __float2half(v.z), __float2half(v.w)};
        ((uint2*)h)[i] = *(uint2*)hh;
    }
}

// ---------------- fused weight splits ([qkv|gate|pre|out], fp16 hi/lo) -------
__global__ void __launch_bounds__(256) wsplit_kernel(
    const float* __restrict__ wq, const float* __restrict__ wg,
    const float* __restrict__ wp, const float* __restrict__ wo,
    __half* __restrict__ hi, __half* __restrict__ lo)
{
    const int id = blockIdx.x;
    const float* src;
    size_t dbase;
    int local;
    if (id < 108)      { src = wq; local = id;       dbase = 0; }
    else if (id < 144) { src = wg; local = id - 108; dbase = (size_t)3 * CC * CC; }
    else if (id < 180) { src = wp; local = id - 144; dbase = (size_t)4 * CC * CC; }
    else               { src = wo; local = id - 180; dbase = (size_t)5 * CC * CC; }
    const int i = local * 256 + threadIdx.x;
    float4 v = ((const float4*)src)[i];
    float vs[4] = {v.x, v.y, v.z, v.w};
    __half h[4], l[4];
#pragma unroll
    for (int j = 0; j < 4; j++) {
        h[j] = __float2half(vs[j]);
        l[j] = __float2half(vs[j] - __half2float(h[j]));
    }
    ((uint2*)(hi + dbase))[i] = *(uint2*)h;
    ((uint2*)(lo + dbase))[i] = *(uint2*)l;
}

// ---------------- fp16 W-split GEMM, cp.async 3-deep pipeline ----------------
// tile 192m x 64n x 16k; 8 warps (4m x 2n); 24 mma/iter/warp.
// epi: 0 f32 out; 1 silu->f32; 2 (*G)->fp16; 3 merged qkv+gate (m0==576 -> silu->G).
#define GA_SLOT 18432
#define GB_BASE 73728
#define GB_SLOT 2304
#define GSMEM   82944

__global__ void __launch_bounds__(256, 2) gemm_fp16_kernel(
    const __half* __restrict__ Whi, const __half* __restrict__ Wlo,
    const __half* __restrict__ Xh,
    float* __restrict__ Yf, float* __restrict__ G,
    __half* __restrict__ Yh, int M, int epi)
{
    extern __shared__ __align__(16) char dsm[];
    const uint32_t sb = smem_u32(dsm);

    const int b  = blockIdx.z;
    const int m0 = blockIdx.y * 192;
    const int n0 = blockIdx.x * 64;
    const size_t xoff = (size_t)b * CC * HWP;

    const int tid  = threadIdx.x;
    const int lane = tid & 31;
    const int warp = tid >> 5;
    const int wm   = (warp >> 1) * 48;
    const int wn   = (warp & 1) * 32;
    const int gq   = lane >> 2;
    const int tg   = lane & 3;

    uint32_t aoff[3];
    size_t   agoff[3];
    const __half* aptr[3];
#pragma unroll
    for (int j = 0; j < 3; j++) {
        const int u = tid + 256 * j;
        const int h = (u >= 384);
        const int v = u - h * 384;
        const int r = v >> 1, c = (v & 1) * 8;
        aoff[j]  = (uint32_t)(h * 9216 + r * 48 + c * 2);
        aptr[j]  = h ? Wlo : Whi;
        agoff[j] = (size_t)(m0 + r) * CC + c;
    }
    const int doB = (tid < 128);
    const int bk = (tid & 127) >> 3, bnc = (tid & 7) * 8;
    const uint32_t boff = (uint32_t)(bk * 144 + bnc * 2);
    const size_t bgoff = xoff + (size_t)bk * HWP + n0 + bnc;

    float acc[3][4][4];
#pragma unroll
    for (int mt = 0; mt < 3; mt++)
#pragma unroll
        for (int nt = 0; nt < 4; nt++)
#pragma unroll
            for (int e = 0; e < 4; e++) acc[mt][nt][e] = 0.f;

#pragma unroll
    for (int s = 0; s < 3; s++) {
        const uint32_t as = sb + s * GA_SLOT;
        const int k0 = s * 16;
#pragma unroll
        for (int j = 0; j < 3; j++) CP_CA(as + aoff[j], aptr[j] + agoff[j] + k0);
        if (doB) CP_CG(sb + GB_BASE + s * GB_SLOT + boff, Xh + bgoff + (size_t)k0 * HWP);
        CP_COMMIT();
    }

    const int NK = CC / 16;
    for (int i = 0; i < NK; i++) {
        CP_WAIT2();
        __syncthreads();
        if (i + 3 < NK) {
            const int s = (i + 3) & 3;
            const int k0 = (i + 3) * 16;
            const uint32_t as = sb + s * GA_SLOT;
#pragma unroll
            for (int j = 0; j < 3; j++) CP_CA(as + aoff[j], aptr[j] + agoff[j] + k0);
            if (doB) CP_CG(sb + GB_BASE + s * GB_SLOT + boff, Xh + bgoff + (size_t)k0 * HWP);
        }
        CP_COMMIT();

        const uint32_t As = sb + (uint32_t)(i & 3) * GA_SLOT;
        const uint32_t Bs = sb + GB_BASE + (uint32_t)(i & 3) * GB_SLOT;

        uint32_t bf[4][2];
        {
            const uint32_t brow = (uint32_t)(lane & 15) * 144 + (uint32_t)wn * 2;
#pragma unroll
            for (int nt = 0; nt < 4; nt++)
                ldsm_x2_t(bf[nt][0], bf[nt][1], Bs + brow + nt * 16);
        }
#pragma unroll
        for (int mt = 0; mt < 3; mt++) {
            uint32_t afh[4], afl[4];
            const uint32_t arow = (uint32_t)(wm + mt * 16 + (lane & 15)) * 48
                                + (uint32_t)((lane >> 4) * 16);
            ldsm_x4(afh, As + arow);
            ldsm_x4(afl, As + 9216 + arow);
#pragma unroll
            for (int nt = 0; nt < 4; nt++) {
                mma16816h(acc[mt][nt], afh, bf[nt][0], bf[nt][1]);
                mma16816h(acc[mt][nt], afl, bf[nt][0], bf[nt][1]);
            }
        }
    }

    const size_t yoff = (size_t)b * M * HWP;
    const size_t goff = (size_t)b * CC * HWP;
    const int gateBlk = (epi == 3 && m0 == 576);
#pragma unroll
    for (int mt = 0; mt < 3; mt++) {
        const int r0 = m0 + wm + mt * 16 + gq;
        const int r1 = r0 + 8;
#pragma unroll
        for (int nt = 0; nt < 4; nt++) {
            const int c = n0 + wn + nt * 8 + 2 * tg;
            float v00 = acc[mt][nt][0], v01 = acc[mt][nt][1];
            float v10 = acc[mt][nt][2], v11 = acc[mt][nt][3];
            if (epi == 1 || gateBlk) {
                v00 = v00 / (1.f + __expf(-v00));
                v01 = v01 / (1.f + __expf(-v01));
                v10 = v10 / (1.f + __expf(-v10));
                v11 = v11 / (1.f + __expf(-v11));
            }
            if (epi == 2) {
                float2 g0 = *(const float2*)(G + goff + (size_t)r0 * HWP + c);
                float2 g1 = *(const float2*)(G + goff + (size_t)r1 * HWP + c);
                v00 *= g0.x; v01 *= g0.y; v10 *= g1.x; v11 *= g1.y;
                *(uint32_t*)(Yh + yoff + (size_t)r0 * HWP + c) =
                    pack_h2(__float2half(v00), __float2half(v01));
                *(uint32_t*)(Yh + yoff + (size_t)r1 * HWP + c) =
                    pack_h2(__float2half(v10), __float2half(v11));
            } else if (gateBlk) {
                *(float2*)(G + goff + (size_t)(r0 - 576) * HWP + c) = make_float2(v00, v01);
                *(float2*)(G + goff + (size_t)(r1 - 576) * HWP + c) = make_float2(v10, v11);
            } else {
                *(float2*)(Yf + yoff + (size_t)r0 * HWP + c) = make_float2(v00, v01);
                *(float2*)(Yf + yoff + (size_t)r1 * HWP + c) = make_float2(v10, v11);
            }
        }
    }
}

// ---------------- depthwise 3x3, 4x8 patch/thread -> fp16 --------------------
__global__ void __launch_bounds__(256) dw_kernel(
    const float* __restrict__ t, const float* __restrict__ wd,
    __half* __restrict__ oh)
{
    const int cb = blockIdx.y;
    const int c  = cb % (3 * CC);
    const int tx = threadIdx.x;
    const int x  = (tx & 31) * 8;
    const int yq = blockIdx.x * 32 + (tx >> 5) * 4;
    const float* base = t + (size_t)cb * HWP;

    float w[9];
#pragma unroll
    for (int i = 0; i < 9; i++) w[i] = wd[c * 9 + i];

    float acc[4][8];
#pragma unroll
    for (int o = 0; o < 4; o++)
#pragma unroll
        for (int i = 0; i < 8; i++) acc[o][i] = 0.f;

#pragma unroll
    for (int ry = -1; ry <= 4; ry++) {
        const int yy = yq + ry;
        if (yy < 0 || yy >= HH) continue;
        const float* r = base + yy * WW + x;
        const float4 f0 = *(const float4*)r;
        const float4 f1 = *(const float4*)(r + 4);
        float v[10];
        v[0] = (x > 0) ? r[-1] : 0.f;
        v[1] = f0.x; v[2] = f0.y; v[3] = f0.z; v[4] = f0.w;
        v[5] = f1.x; v[6] = f1.y; v[7] = f1.z; v[8] = f1.w;
        v[9] = (x < 248) ? r[8] : 0.f;
#pragma unroll
        for (int o = 0; o < 4; o++) {
            const int d = ry - o;
            if (d < -1 || d > 1) continue;
            const int wr = (d + 1) * 3;
#pragma unroll
            for (int i = 0; i < 8; i++)
                acc[o][i] = fmaf(w[wr], v[i],
                            fmaf(w[wr + 1], v[i + 1],
                            fmaf(w[wr + 2], v[i + 2], acc[o][i])));
        }
    }
#pragma unroll
    for (int o = 0; o < 4; o++) {
        __half h[8];
#pragma unroll
        for (int i = 0; i < 8; i++) h[i] = __float2half(acc[o][i]);
        *(uint4*)(oh + (size_t)cb * HWP + (yq + o) * WW + x) = *(uint4*)h;
    }
}

// ---------------- attention, fp16, cp.async double-buffered K/V --------------
__global__ void __launch_bounds__(256, 2) attn_mma_kernel(
    const __half* __restrict__ qv, const float* __restrict__ rpb,
    __half* __restrict__ oa)
{
    __shared__ float bsh[512];
    __shared__ __align__(16) __half KV[2][2][32][72];  // [slot][K/V][d][j]
    __shared__ __align__(16) float stage[128 * 33];

    const int row = blockIdx.x;
    const int head = blockIdx.y % 6, qh = blockIdx.y / 6;
    const int b = blockIdx.z;
    const int tid = threadIdx.x, lane = tid & 31, warp = tid >> 5;
    const int gq = lane >> 2, tg = lane & 3;
    const size_t base = (((size_t)b * (3 * CC) + head * 32) * HH + row) * WW;
    const size_t koff = (size_t)CC * HWP;
    const float scale2 = 0.17677669529663687f * LOG2E;

    const int cd = tid >> 3, cj = (tid & 7) * 8;
    // issue chunk 0 immediately (overlaps Q staging + bias load)
    {
        const size_t kb = base + koff + (size_t)cd * HWP + 0 + cj;
        CP_CG(smem_u32(&KV[0][0][cd][cj]), qv + kb);
        CP_CG(smem_u32(&KV[0][1][cd][cj]), qv + kb + koff);
        CP_COMMIT();
    }

    for (int i = tid; i < 511; i += 256) bsh[i] = rpb[i * 6 + head] * LOG2E;

    // ---- stage Q through `stage`, build A fragments ----
    uint32_t qf[2][4];
    {
        __half* Qst = (__half*)stage;                 // [32][136]
        const int d = tid >> 3, q16 = (tid & 7) * 16;
        const size_t go = base + (size_t)d * HWP + qh * 128 + q16;
        uint4 v0 = *(const uint4*)(qv + go);
        uint4 v1 = *(const uint4*)(qv + go + 8);
        *(uint4*)&Qst[d * 136 + q16] = v0;
        *(uint4*)&Qst[d * 136 + q16 + 8] = v1;
        __syncthreads();
        const int lrow = ((lane >> 4) & 1) * 8 + (lane & 7);
        const int lcol = warp * 16 + ((lane >> 3) & 1) * 8;
#pragma unroll
        for (int ks = 0; ks < 2; ks++)
            ldsm_x4_t(qf[ks], smem_u32(&Qst[(ks * 16 + lrow) * 136 + lcol]));
        __syncthreads();
    }

    float m2[2] = {-1e30f, -1e30f}, l2[2] = {0.f, 0.f};
    float o[4][4];
#pragma unroll
    for (int nt = 0; nt < 4; nt++)
#pragma unroll
        for (int e = 0; e < 4; e++) o[nt][e] = 0.f;

    for (int ic = 0; ic < 4; ic++) {
        const int jt = ic * 64;
        const int sl = ic & 1;
        if (ic + 1 < 4) {
            const size_t kb = base + koff + (size_t)cd * HWP + jt + 64 + cj;
            CP_CG(smem_u32(&KV[sl ^ 1][0][cd][cj]), qv + kb);
            CP_CG(smem_u32(&KV[sl ^ 1][1][cd][cj]), qv + kb + koff);
            CP_COMMIT();
            CP_WAIT1();
        } else {
            CP_WAIT0();
        }
        __syncthreads();

        // S = Q K^T
        float s[8][4];
#pragma unroll
        for (int nt = 0; nt < 8; nt++)
#pragma unroll
            for (int e = 0; e < 4; e++) s[nt][e] = 0.f;
        const int krow = lane & 15;
#pragma unroll
        for (int ks = 0; ks < 2; ks++) {
            const uint32_t kb0 = smem_u32(&KV[sl][0][ks * 16 + krow][0]);
#pragma unroll
            for (int nt = 0; nt < 8; nt++) {
                uint32_t h0, h1;
                ldsm_x2_t(h0, h1, kb0 + nt * 16);
                mma16816h(s[nt], qf[ks], h0, h1);
            }
        }

        float mx[2] = {m2[0], m2[1]};
        const int i0 = qh * 128 + warp * 16 + gq;
#pragma unroll
        for (int nt = 0; nt < 8; nt++) {
            const int jb = jt + nt * 8 + 2 * tg;
#pragma unroll
            for (int e = 0; e < 4; e++) {
                const int i = i0 + (e >> 1) * 8;
                const int j = jb + (e & 1);
                const float t = fmaf(s[nt][e], scale2, bsh[i - j + 255]);
                s[nt][e] = t;
                mx[e >> 1] = fmaxf(mx[e >> 1], t);
            }
        }
#pragma unroll
        for (int slx = 0; slx < 2; slx++) {
            float v = mx[slx];
            v = fmaxf(v, __shfl_xor_sync(0xFFFFFFFFu, v, 1));
            v = fmaxf(v, __shfl_xor_sync(0xFFFFFFFFu, v, 2));
            mx[slx] = v;
        }
        float cf[2];
#pragma unroll
        for (int slx = 0; slx < 2; slx++) {
            cf[slx] = exp2f(m2[slx] - mx[slx]);
            m2[slx] = mx[slx];
            l2[slx] *= cf[slx];
        }
#pragma unroll
        for (int nt = 0; nt < 4; nt++)
#pragma unroll
            for (int e = 0; e < 4; e++) o[nt][e] *= cf[e >> 1];

        // P = exp2(S - m); PV
        float rs[2] = {0.f, 0.f};
#pragma unroll
        for (int kp = 0; kp < 4; kp++) {
            uint32_t pf[4];
#pragma unroll
            for (int h2 = 0; h2 < 2; h2++) {
                const int nt = 2 * kp + h2;
                float p0 = exp2f(s[nt][0] - m2[0]);
                float p1 = exp2f(s[nt][1] - m2[0]);
                float p2 = exp2f(s[nt][2] - m2[1]);
                float p3 = exp2f(s[nt][3] - m2[1]);
                rs[0] += p0 + p1;
                rs[1] += p2 + p3;
                pf[h2 * 2 + 0] = pack_h2(__float2half(p0), __float2half(p1));
                pf[h2 * 2 + 1] = pack_h2(__float2half(p2), __float2half(p3));
            }
            const int vr = lane & 7, vk = kp * 16 + ((lane >> 3) & 1) * 8;
#pragma unroll
            for (int ntv = 0; ntv < 4; ntv++) {
                uint32_t v0, v1;
                ldsm_x2(v0, v1, smem_u32(&KV[sl][1][ntv * 8 + vr][vk]));
                mma16816h(o[ntv], pf, v0, v1);
            }
        }
#pragma unroll
        for (int slx = 0; slx < 2; slx++) {
            float r = rs[slx];
            r += __shfl_xor_sync(0xFFFFFFFFu, r, 1);
            r += __shfl_xor_sync(0xFFFFFFFFu, r, 2);
            l2[slx] += r;
        }
        __syncthreads();
    }

    const float inv0 = 1.f / l2[0], inv1 = 1.f / l2[1];
#pragma unroll
    for (int nt = 0; nt < 4; nt++) {
        const int c = nt * 8 + 2 * tg;
#pragma unroll
        for (int e = 0; e < 4; e++) {
            const int rr = warp * 16 + gq + (e >> 1) * 8;
            stage[rr * 33 + c + (e & 1)] = o[nt][e] * ((e >> 1) ? inv1 : inv0);
        }
    }
    __syncthreads();
    const size_t obase = (((size_t)b * CC + head * 32) * HH + row) * WW + qh * 128;
    const int q = tid & 127, db = (tid >> 7) * 16;
#pragma unroll
    for (int dd = 0; dd < 16; dd++) {
        const int d = db + dd;
        oa[obase + (size_t)d * HWP + q] = __float2half(stage[q * 33 + d]);
    }
}

// ---------------- launch ------------------------------------------------------
extern "C" void kernel_launch(void* const* d_in, const int* in_sizes, int n_in,
                              void* d_out, int out_size)
{
    const float* x       = (const float*)d_in[0];
    const float* rpb     = (const float*)d_in[1];
    const float* w_qkv   = (const float*)d_in[2];
    const float* w_depth = (const float*)d_in[3];
    const float* w_pre   = (const float*)d_in[4];
    const float* w_out   = (const float*)d_in[5];
    const float* w_gate  = (const float*)d_in[6];
    float* out = (float*)d_out;
    (void)in_sizes; (void)n_in; (void)out_size;

    float *gate, *t;
    __half *qv, *xh, *ah, *yh, *whi, *wlo;
    cudaGetSymbolAddress((void**)&gate, g_gate);
    cudaGetSymbolAddress((void**)&t,    g_t);
    cudaGetSymbolAddress((void**)&qv,   g_qv);
    cudaGetSymbolAddress((void**)&xh,   g_xh);
    cudaGetSymbolAddress((void**)&ah,   g_ah);
    cudaGetSymbolAddress((void**)&yh,   g_yh);
    cudaGetSymbolAddress((void**)&whi,  g_whi);
    cudaGetSymbolAddress((void**)&wlo,  g_wlo);

    cudaFuncSetAttribute(gemm_fp16_kernel,
                         cudaFuncAttributeMaxDynamicSharedMemorySize, GSMEM);

    const int WS = CC * CC;
    const int nx = NB * CC * HWP;
    cvt4_kernel<<<(nx / 4 + 255) / 256, 256>>>(x, xh, nx / 4);
    wsplit_kernel<<<216, 256>>>(w_qkv, w_gate, w_pre, w_out, whi, wlo);

    const dim3 gSmall(HWP / 64, 1, NB);
    const dim3 gMerged(HWP / 64, 4, NB);     // M=768: qkv(576) + gate(192)

    // [t | gate] = [W_qkv; W_gate] @ x   (gate rows get silu)
    gemm_fp16_kernel<<<gMerged, 256, GSMEM>>>(whi, wlo, xh,
                                              t, gate, nullptr, 3 * CC, 3);
    // q,k,v = depthwise3x3(t) -> fp16
    dw_kernel<<<dim3(HH / 32, NB * 3 * CC), 256>>>(t, w_depth, qv);
    // attention -> fp16
    attn_mma_kernel<<<dim3(HH, 12, NB), 256>>>(qv, rpb, ah);
    // y = (W_pre @ attn) * gate -> fp16
    gemm_fp16_kernel<<<gSmall, 256, GSMEM>>>(whi + 4 * WS, wlo + 4 * WS, ah,
                                             nullptr, gate, yh, CC, 2);
    // out = W_out @ y
    gemm_fp16_kernel<<<gSmall, 256, GSMEM>>>(whi + 5 * WS, wlo + 5 * WS, yh,
                                             out, nullptr, nullptr, CC, 0);
}

// round 11
// speedup vs baseline: 2.9062x; 1.0321x over previous
#include <cuda_runtime.h>
#include <cuda_bf16.h>
#include <cuda_fp16.h>
#include <math.h>
#include <stdint.h>

#define HH 128
#define WW 256
#define CC 192
#define HWP (128*256)
#define NB 2
#define LOG2E 1.4426950408889634f

// ---------------- scratch (device globals) ----------------------------------
__device__ float g_gate[NB * CC * HWP];
__device__ __half g_t[NB * 3 * CC * HWP];      // qkv pre-dw, fp16
__device__ __half g_qv[NB * 3 * CC * HWP];     // q,k,v fp16 (dw output)
__device__ __half g_xh[NB * CC * HWP];         // x fp16
__device__ __half g_ah[NB * CC * HWP];         // attn out fp16
__device__ __half g_yh[NB * CC * HWP];         // pre*gate fp16
__device__ __half g_whi[6 * CC * CC];          // [qkv|gate|pre|out]
__device__ __half g_wlo[6 * CC * CC];

// ---------------- helpers -----------------------------------------------------
__device__ __forceinline__ uint32_t smem_u32(const void* p) {
    uint32_t a;
    asm("{ .reg .u64 t; cvta.to.shared.u64 t, %1; cvt.u32.u64 %0, t; }" : "=r"(a) : "l"(p));
    return a;
}
__device__ __forceinline__ void mma16816h(float* c, const uint32_t* a,
                                          uint32_t b0, uint32_t b1)
{
    asm volatile(
        "mma.sync.aligned.m16n8k16.row.col.f32.f16.f16.f32 "
        "{%0,%1,%2,%3}, {%4,%5,%6,%7}, {%8,%9}, {%0,%1,%2,%3};\n"
        : "+f"(c[0]), "+f"(c[1]), "+f"(c[2]), "+f"(c[3])
        : "r"(a[0]), "r"(a[1]), "r"(a[2]), "r"(a[3]), "r"(b0), "r"(b1));
}
__device__ __forceinline__ void ldsm_x4(uint32_t* d, uint32_t a) {
    asm volatile("ldmatrix.sync.aligned.m8n8.x4.shared.b16 {%0,%1,%2,%3}, [%4];\n"
                 : "=r"(d[0]), "=r"(d[1]), "=r"(d[2]), "=r"(d[3]) : "r"(a));
}
__device__ __forceinline__ void ldsm_x4_t(uint32_t* d, uint32_t a) {
    asm volatile("ldmatrix.sync.aligned.m8n8.x4.trans.shared.b16 {%0,%1,%2,%3}, [%4];\n"
                 : "=r"(d[0]), "=r"(d[1]), "=r"(d[2]), "=r"(d[3]) : "r"(a));
}
__device__ __forceinline__ void ldsm_x2(uint32_t& d0, uint32_t& d1, uint32_t a) {
    asm volatile("ldmatrix.sync.aligned.m8n8.x2.shared.b16 {%0,%1}, [%2];\n"
                 : "=r"(d0), "=r"(d1) : "r"(a));
}
__device__ __forceinline__ void ldsm_x2_t(uint32_t& d0, uint32_t& d1, uint32_t a) {
    asm volatile("ldmatrix.sync.aligned.m8n8.x2.trans.shared.b16 {%0,%1}, [%2];\n"
                 : "=r"(d0), "=r"(d1) : "r"(a));
}
__device__ __forceinline__ uint32_t pack_h2(__half a, __half b) {
    __half2 t = __halves2half2(a, b);
    return *(uint32_t*)&t;
}
#define CP_CA(d, s) asm volatile("cp.async.ca.shared.global [%0], [%1], 16;\n" :: "r"(d), "l"(s))
#define CP_CG(d, s) asm volatile("cp.async.cg.shared.global [%0], [%1], 16;\n" :: "r"(d), "l"(s))
#define CP_COMMIT() asm volatile("cp.async.commit_group;\n" ::: "memory")
#define CP_WAIT2()  asm volatile("cp.async.wait_group 2;\n" ::: "memory")
#define CP_WAIT1()  asm volatile("cp.async.wait_group 1;\n" ::: "memory")
#define CP_WAIT0()  asm volatile("cp.async.wait_group 0;\n" ::: "memory")

// ---------------- fp32 -> fp16, 4/thread -------------------------------------
__global__ void __launch_bounds__(256) cvt4_kernel(
    const float* __restrict__ x, __half* __restrict__ h, int n4)
{
    int i = blockIdx.x * 256 + threadIdx.x;
    if (i < n4) {
        float4 v = ((const float4*)x)[i];
        __half hh[4] = {__float2half(v.x), __float2half(v.y),
                        __float2half(v.z), __float2half(v.w)};
        ((uint2*)h)[i] = *(uint2*)hh;
    }
}

// ---------------- fused weight splits ([qkv|gate|pre|out], fp16 hi/lo) -------
__global__ void __launch_bounds__(256) wsplit_kernel(
    const float* __restrict__ wq, const float* __restrict__ wg,
    const float* __restrict__ wp, const float* __restrict__ wo,
    __half* __restrict__ hi, __half* __restrict__ lo)
{
    const int id = blockIdx.x;
    const float* src;
    size_t dbase;
    int local;
    if (id < 108)      { src = wq; local = id;       dbase = 0; }
    else if (id < 144) { src = wg; local = id - 108; dbase = (size_t)3 * CC * CC; }
    else if (id < 180) { src = wp; local = id - 144; dbase = (size_t)4 * CC * CC; }
    else               { src = wo; local = id - 180; dbase = (size_t)5 * CC * CC; }
    const int i = local * 256 + threadIdx.x;
    float4 v = ((const float4*)src)[i];
    float vs[4] = {v.x, v.y, v.z, v.w};
    __half h[4], l[4];
#pragma unroll
    for (int j = 0; j < 4; j++) {
        h[j] = __float2half(vs[j]);
        l[j] = __float2half(vs[j] - __half2float(h[j]));
    }
    ((uint2*)(hi + dbase))[i] = *(uint2*)h;
    ((uint2*)(lo + dbase))[i] = *(uint2*)l;
}

// ---------------- fp16 W-split GEMM, cp.async 3-deep pipeline ----------------
// tile 192m x 64n x 16k; 8 warps (4m x 2n); 24 mma/iter/warp.
// epi: 0 f32 out; 2 (*G f32)->fp16; 3 merged: rows<576 -> fp16 Yh, rows>=576 -> silu -> f32 G.
#define GA_SLOT 18432
#define GB_BASE 73728
#define GB_SLOT 2304
#define GSMEM   82944

__global__ void __launch_bounds__(256, 2) gemm_fp16_kernel(
    const __half* __restrict__ Whi, const __half* __restrict__ Wlo,
    const __half* __restrict__ Xh,
    float* __restrict__ Yf, float* __restrict__ G,
    __half* __restrict__ Yh, int M, int epi)
{
    extern __shared__ __align__(16) char dsm[];
    const uint32_t sb = smem_u32(dsm);

    const int b  = blockIdx.z;
    const int m0 = blockIdx.y * 192;
    const int n0 = blockIdx.x * 64;
    const size_t xoff = (size_t)b * CC * HWP;

    const int tid  = threadIdx.x;
    const int lane = tid & 31;
    const int warp = tid >> 5;
    const int wm   = (warp >> 1) * 48;
    const int wn   = (warp & 1) * 32;
    const int gq   = lane >> 2;
    const int tg   = lane & 3;

    uint32_t aoff[3];
    size_t   agoff[3];
    const __half* aptr[3];
#pragma unroll
    for (int j = 0; j < 3; j++) {
        const int u = tid + 256 * j;
        const int h = (u >= 384);
        const int v = u - h * 384;
        const int r = v >> 1, c = (v & 1) * 8;
        aoff[j]  = (uint32_t)(h * 9216 + r * 48 + c * 2);
        aptr[j]  = h ? Wlo : Whi;
        agoff[j] = (size_t)(m0 + r) * CC + c;
    }
    const int doB = (tid < 128);
    const int bk = (tid & 127) >> 3, bnc = (tid & 7) * 8;
    const uint32_t boff = (uint32_t)(bk * 144 + bnc * 2);
    const size_t bgoff = xoff + (size_t)bk * HWP + n0 + bnc;

    float acc[3][4][4];
#pragma unroll
    for (int mt = 0; mt < 3; mt++)
#pragma unroll
        for (int nt = 0; nt < 4; nt++)
#pragma unroll
            for (int e = 0; e < 4; e++) acc[mt][nt][e] = 0.f;

#pragma unroll
    for (int s = 0; s < 3; s++) {
        const uint32_t as = sb + s * GA_SLOT;
        const int k0 = s * 16;
#pragma unroll
        for (int j = 0; j < 3; j++) CP_CA(as + aoff[j], aptr[j] + agoff[j] + k0);
        if (doB) CP_CG(sb + GB_BASE + s * GB_SLOT + boff, Xh + bgoff + (size_t)k0 * HWP);
        CP_COMMIT();
    }

    const int NK = CC / 16;
    for (int i = 0; i < NK; i++) {
        CP_WAIT2();
        __syncthreads();
        if (i + 3 < NK) {
            const int s = (i + 3) & 3;
            const int k0 = (i + 3) * 16;
            const uint32_t as = sb + s * GA_SLOT;
#pragma unroll
            for (int j = 0; j < 3; j++) CP_CA(as + aoff[j], aptr[j] + agoff[j] + k0);
            if (doB) CP_CG(sb + GB_BASE + s * GB_SLOT + boff, Xh + bgoff + (size_t)k0 * HWP);
        }
        CP_COMMIT();

        const uint32_t As = sb + (uint32_t)(i & 3) * GA_SLOT;
        const uint32_t Bs = sb + GB_BASE + (uint32_t)(i & 3) * GB_SLOT;

        uint32_t bf[4][2];
        {
            const uint32_t brow = (uint32_t)(lane & 15) * 144 + (uint32_t)wn * 2;
#pragma unroll
            for (int nt = 0; nt < 4; nt++)
                ldsm_x2_t(bf[nt][0], bf[nt][1], Bs + brow + nt * 16);
        }
#pragma unroll
        for (int mt = 0; mt < 3; mt++) {
            uint32_t afh[4], afl[4];
            const uint32_t arow = (uint32_t)(wm + mt * 16 + (lane & 15)) * 48
                                + (uint32_t)((lane >> 4) * 16);
            ldsm_x4(afh, As + arow);
            ldsm_x4(afl, As + 9216 + arow);
#pragma unroll
            for (int nt = 0; nt < 4; nt++) {
                mma16816h(acc[mt][nt], afh, bf[nt][0], bf[nt][1]);
                mma16816h(acc[mt][nt], afl, bf[nt][0], bf[nt][1]);
            }
        }
    }

    const size_t yoff = (size_t)b * M * HWP;
    const size_t goff = (size_t)b * CC * HWP;
    const int gateBlk = (epi == 3 && m0 == 576);
#pragma unroll
    for (int mt = 0; mt < 3; mt++) {
        const int r0 = m0 + wm + mt * 16 + gq;
        const int r1 = r0 + 8;
#pragma unroll
        for (int nt = 0; nt < 4; nt++) {
            const int c = n0 + wn + nt * 8 + 2 * tg;
            float v00 = acc[mt][nt][0], v01 = acc[mt][nt][1];
            float v10 = acc[mt][nt][2], v11 = acc[mt][nt][3];
            if (gateBlk) {
                v00 = v00 / (1.f + __expf(-v00));
                v01 = v01 / (1.f + __expf(-v01));
                v10 = v10 / (1.f + __expf(-v10));
                v11 = v11 / (1.f + __expf(-v11));
                *(float2*)(G + goff + (size_t)(r0 - 576) * HWP + c) = make_float2(v00, v01);
                *(float2*)(G + goff + (size_t)(r1 - 576) * HWP + c) = make_float2(v10, v11);
            } else if (epi == 3) {
                *(uint32_t*)(Yh + yoff + (size_t)r0 * HWP + c) =
                    pack_h2(__float2half(v00), __float2half(v01));
                *(uint32_t*)(Yh + yoff + (size_t)r1 * HWP + c) =
                    pack_h2(__float2half(v10), __float2half(v11));
            } else if (epi == 2) {
                float2 g0 = *(const float2*)(G + goff + (size_t)r0 * HWP + c);
                float2 g1 = *(const float2*)(G + goff + (size_t)r1 * HWP + c);
                v00 *= g0.x; v01 *= g0.y; v10 *= g1.x; v11 *= g1.y;
                *(uint32_t*)(Yh + yoff + (size_t)r0 * HWP + c) =
                    pack_h2(__float2half(v00), __float2half(v01));
                *(uint32_t*)(Yh + yoff + (size_t)r1 * HWP + c) =
                    pack_h2(__float2half(v10), __float2half(v11));
            } else {
                *(float2*)(Yf + yoff + (size_t)r0 * HWP + c) = make_float2(v00, v01);
                *(float2*)(Yf + yoff + (size_t)r1 * HWP + c) = make_float2(v10, v11);
            }
        }
    }
}

// ---------------- depthwise 3x3, 4x8 patch/thread, fp16 in/out ---------------
__global__ void __launch_bounds__(256) dw_kernel(
    const __half* __restrict__ t, const float* __restrict__ wd,
    __half* __restrict__ oh)
{
    const int cb = blockIdx.y;
    const int c  = cb % (3 * CC);
    const int tx = threadIdx.x;
    const int x  = (tx & 31) * 8;
    const int yq = blockIdx.x * 32 + (tx >> 5) * 4;
    const __half* base = t + (size_t)cb * HWP;

    float w[9];
#pragma unroll
    for (int i = 0; i < 9; i++) w[i] = wd[c * 9 + i];

    float acc[4][8];
#pragma unroll
    for (int o = 0; o < 4; o++)
#pragma unroll
        for (int i = 0; i < 8; i++) acc[o][i] = 0.f;

#pragma unroll
    for (int ry = -1; ry <= 4; ry++) {
        const int yy = yq + ry;
        if (yy < 0 || yy >= HH) continue;
        const __half* r = base + yy * WW + x;
        uint4 u = *(const uint4*)r;               // 8 halves
        __half hv[8];
        *(uint4*)hv = u;
        float v[10];
        v[0] = (x > 0) ? __half2float(r[-1]) : 0.f;
#pragma unroll
        for (int i = 0; i < 8; i++) v[i + 1] = __half2float(hv[i]);
        v[9] = (x < 248) ? __half2float(r[8]) : 0.f;
#pragma unroll
        for (int o = 0; o < 4; o++) {
            const int d = ry - o;
            if (d < -1 || d > 1) continue;
            const int wr = (d + 1) * 3;
#pragma unroll
            for (int i = 0; i < 8; i++)
                acc[o][i] = fmaf(w[wr], v[i],
                            fmaf(w[wr + 1], v[i + 1],
                            fmaf(w[wr + 2], v[i + 2], acc[o][i])));
        }
    }
#pragma unroll
    for (int o = 0; o < 4; o++) {
        __half h[8];
#pragma unroll
        for (int i = 0; i < 8; i++) h[i] = __float2half(acc[o][i]);
        *(uint4*)(oh + (size_t)cb * HWP + (yq + o) * WW + x) = *(uint4*)h;
    }
}

// ---------------- attention, fp16, cp.async double-buffered K/V --------------
__global__ void __launch_bounds__(256, 2) attn_mma_kernel(
    const __half* __restrict__ qv, const float* __restrict__ rpb,
    __half* __restrict__ oa)
{
    __shared__ float bsh[512];
    __shared__ __align__(16) __half KV[2][2][32][72];  // [slot][K/V][d][j]
    __shared__ __align__(16) float stage[128 * 33];

    const int row = blockIdx.x;
    const int head = blockIdx.y % 6, qh = blockIdx.y / 6;
    const int b = blockIdx.z;
    const int tid = threadIdx.x, lane = tid & 31, warp = tid >> 5;
    const int gq = lane >> 2, tg = lane & 3;
    const size_t base = (((size_t)b * (3 * CC) + head * 32) * HH + row) * WW;
    const size_t koff = (size_t)CC * HWP;
    const float scale2 = 0.17677669529663687f * LOG2E;

    const int cd = tid >> 3, cj = (tid & 7) * 8;
    {
        const size_t kb = base + koff + (size_t)cd * HWP + 0 + cj;
        CP_CG(smem_u32(&KV[0][0][cd][cj]), qv + kb);
        CP_CG(smem_u32(&KV[0][1][cd][cj]), qv + kb + koff);
        CP_COMMIT();
    }

    for (int i = tid; i < 511; i += 256) bsh[i] = rpb[i * 6 + head] * LOG2E;

    uint32_t qf[2][4];
    {
        __half* Qst = (__half*)stage;                 // [32][136]
        const int d = tid >> 3, q16 = (tid & 7) * 16;
        const size_t go = base + (size_t)d * HWP + qh * 128 + q16;
        uint4 v0 = *(const uint4*)(qv + go);
        uint4 v1 = *(const uint4*)(qv + go + 8);
        *(uint4*)&Qst[d * 136 + q16] = v0;
        *(uint4*)&Qst[d * 136 + q16 + 8] = v1;
        __syncthreads();
        const int lrow = ((lane >> 4) & 1) * 8 + (lane & 7);
        const int lcol = warp * 16 + ((lane >> 3) & 1) * 8;
#pragma unroll
        for (int ks = 0; ks < 2; ks++)
            ldsm_x4_t(qf[ks], smem_u32(&Qst[(ks * 16 + lrow) * 136 + lcol]));
        __syncthreads();
    }

    float m2[2] = {-1e30f, -1e30f}, l2[2] = {0.f, 0.f};
    float o[4][4];
#pragma unroll
    for (int nt = 0; nt < 4; nt++)
#pragma unroll
        for (int e = 0; e < 4; e++) o[nt][e] = 0.f;

    for (int ic = 0; ic < 4; ic++) {
        const int jt = ic * 64;
        const int sl = ic & 1;
        if (ic + 1 < 4) {
            const size_t kb = base + koff + (size_t)cd * HWP + jt + 64 + cj;
            CP_CG(smem_u32(&KV[sl ^ 1][0][cd][cj]), qv + kb);
            CP_CG(smem_u32(&KV[sl ^ 1][1][cd][cj]), qv + kb + koff);
            CP_COMMIT();
            CP_WAIT1();
        } else {
            CP_WAIT0();
        }
        __syncthreads();

        float s[8][4];
#pragma unroll
        for (int nt = 0; nt < 8; nt++)
#pragma unroll
            for (int e = 0; e < 4; e++) s[nt][e] = 0.f;
        const int krow = lane & 15;
#pragma unroll
        for (int ks = 0; ks < 2; ks++) {
            const uint32_t kb0 = smem_u32(&KV[sl][0][ks * 16 + krow][0]);
#pragma unroll
            for (int nt = 0; nt < 8; nt++) {
                uint32_t h0, h1;
                ldsm_x2_t(h0, h1, kb0 + nt * 16);
                mma16816h(s[nt], qf[ks], h0, h1);
            }
        }

        float mx[2] = {m2[0], m2[1]};
        const int i0 = qh * 128 + warp * 16 + gq;
#pragma unroll
        for (int nt = 0; nt < 8; nt++) {
            const int jb = jt + nt * 8 + 2 * tg;
#pragma unroll
            for (int e = 0; e < 4; e++) {
                const int i = i0 + (e >> 1) * 8;
                const int j = jb + (e & 1);
                const float t = fmaf(s[nt][e], scale2, bsh[i - j + 255]);
                s[nt][e] = t;
                mx[e >> 1] = fmaxf(mx[e >> 1], t);
            }
        }
#pragma unroll
        for (int slx = 0; slx < 2; slx++) {
            float v = mx[slx];
            v = fmaxf(v, __shfl_xor_sync(0xFFFFFFFFu, v, 1));
            v = fmaxf(v, __shfl_xor_sync(0xFFFFFFFFu, v, 2));
            mx[slx] = v;
        }
        float cf[2];
#pragma unroll
        for (int slx = 0; slx < 2; slx++) {
            cf[slx] = exp2f(m2[slx] - mx[slx]);
            m2[slx] = mx[slx];
            l2[slx] *= cf[slx];
        }
#pragma unroll
        for (int nt = 0; nt < 4; nt++)
#pragma unroll
            for (int e = 0; e < 4; e++) o[nt][e] *= cf[e >> 1];

        float rs[2] = {0.f, 0.f};
#pragma unroll
        for (int kp = 0; kp < 4; kp++) {
            uint32_t pf[4];
#pragma unroll
            for (int h2 = 0; h2 < 2; h2++) {
                const int nt = 2 * kp + h2;
                float p0 = exp2f(s[nt][0] - m2[0]);
                float p1 = exp2f(s[nt][1] - m2[0]);
                float p2 = exp2f(s[nt][2] - m2[1]);
                float p3 = exp2f(s[nt][3] - m2[1]);
                rs[0] += p0 + p1;
                rs[1] += p2 + p3;
                pf[h2 * 2 + 0] = pack_h2(__float2half(p0), __float2half(p1));
                pf[h2 * 2 + 1] = pack_h2(__float2half(p2), __float2half(p3));
            }
            const int vr = lane & 7, vk = kp * 16 + ((lane >> 3) & 1) * 8;
#pragma unroll
            for (int ntv = 0; ntv < 4; ntv++) {
                uint32_t v0, v1;
                ldsm_x2(v0, v1, smem_u32(&KV[sl][1][ntv * 8 + vr][vk]));
                mma16816h(o[ntv], pf, v0, v1);
            }
        }
#pragma unroll
        for (int slx = 0; slx < 2; slx++) {
            float r = rs[slx];
            r += __shfl_xor_sync(0xFFFFFFFFu, r, 1);
            r += __shfl_xor_sync(0xFFFFFFFFu, r, 2);
            l2[slx] += r;
        }
        __syncthreads();
    }

    const float inv0 = 1.f / l2[0], inv1 = 1.f / l2[1];
#pragma unroll
    for (int nt = 0; nt < 4; nt++) {
        const int c = nt * 8 + 2 * tg;
#pragma unroll
        for (int e = 0; e < 4; e++) {
            const int rr = warp * 16 + gq + (e >> 1) * 8;
            stage[rr * 33 + c + (e & 1)] = o[nt][e] * ((e >> 1) ? inv1 : inv0);
        }
    }
    __syncthreads();
    const size_t obase = (((size_t)b * CC + head * 32) * HH + row) * WW + qh * 128;
    const int q = tid & 127, db = (tid >> 7) * 16;
#pragma unroll
    for (int dd = 0; dd < 16; dd++) {
        const int d = db + dd;
        oa[obase + (size_t)d * HWP + q] = __float2half(stage[q * 33 + d]);
    }
}

// ---------------- launch ------------------------------------------------------
extern "C" void kernel_launch(void* const* d_in, const int* in_sizes, int n_in,
                              void* d_out, int out_size)
{
    const float* x       = (const float*)d_in[0];
    const float* rpb     = (const float*)d_in[1];
    const float* w_qkv   = (const float*)d_in[2];
    const float* w_depth = (const float*)d_in[3];
    const float* w_pre   = (const float*)d_in[4];
    const float* w_out   = (const float*)d_in[5];
    const float* w_gate  = (const float*)d_in[6];
    float* out = (float*)d_out;
    (void)in_sizes; (void)n_in; (void)out_size;

    float* gate;
    __half *th, *qv, *xh, *ah, *yh, *whi, *wlo;
    cudaGetSymbolAddress((void**)&gate, g_gate);
    cudaGetSymbolAddress((void**)&th,   g_t);
    cudaGetSymbolAddress((void**)&qv,   g_qv);
    cudaGetSymbolAddress((void**)&xh,   g_xh);
    cudaGetSymbolAddress((void**)&ah,   g_ah);
    cudaGetSymbolAddress((void**)&yh,   g_yh);
    cudaGetSymbolAddress((void**)&whi,  g_whi);
    cudaGetSymbolAddress((void**)&wlo,  g_wlo);

    cudaFuncSetAttribute(gemm_fp16_kernel,
                         cudaFuncAttributeMaxDynamicSharedMemorySize, GSMEM);

    const int WS = CC * CC;
    const int nx = NB * CC * HWP;
    cvt4_kernel<<<(nx / 4 + 255) / 256, 256>>>(x, xh, nx / 4);
    wsplit_kernel<<<216, 256>>>(w_qkv, w_gate, w_pre, w_out, whi, wlo);

    const dim3 gSmall(HWP / 64, 1, NB);
    const dim3 gMerged(HWP / 64, 4, NB);     // M=768: qkv(576 -> fp16 t) + gate(192 -> silu f32)

    // [t | gate] = [W_qkv; W_gate] @ x
    gemm_fp16_kernel<<<gMerged, 256, GSMEM>>>(whi, wlo, xh,
                                              nullptr, gate, th, 3 * CC, 3);
    // q,k,v = depthwise3x3(t) -> fp16
    dw_kernel<<<dim3(HH / 32, NB * 3 * CC), 256>>>(th, w_depth, qv);
    // attention -> fp16
    attn_mma_kernel<<<dim3(HH, 12, NB), 256>>>(qv, rpb, ah);
    // y = (W_pre @ attn) * gate -> fp16
    gemm_fp16_kernel<<<gSmall, 256, GSMEM>>>(whi + 4 * WS, wlo + 4 * WS, ah,
                                             nullptr, gate, yh, CC, 2);
    // out = W_out @ y
    gemm_fp16_kernel<<<gSmall, 256, GSMEM>>>(whi + 5 * WS, wlo + 5 * WS, yh,
                                             out, nullptr, nullptr, CC, 0);
}